// round 2
// baseline (speedup 1.0000x reference)
#include <cuda_runtime.h>
#include <math.h>

#define B_     16
#define LQ     4096
#define LK     77
#define DMODEL 512
#define DCOND  768
#define NH     8
#define HD     64
#define INNER  512   // NH*HD

// Scratch (allocation-free rule: __device__ globals)
__device__ float g_Q[(size_t)B_ * LQ * INNER];     // 128 MB
__device__ float g_attn[(size_t)B_ * LQ * INNER];  // 128 MB
__device__ float g_K[B_ * LK * INNER];
__device__ float g_V[B_ * LK * INNER];

// ---------------------------------------------------------------------------
// C[M,N] = A[M,K] @ B[N,K]^T   (both row-major, K contiguous — "NT" GEMM)
// 128x128 tile, BK=8, 256 threads, 8x8 microtile, register prefetch pipeline.
// GUARD: bounds-check M (used for the 1232-row cond projections).
// Requires: K % 8 == 0, N % 128 == 0.
// ---------------------------------------------------------------------------
template <bool GUARD>
__global__ __launch_bounds__(256, 2)
void sgemm_nt(const float* __restrict__ A, const float* __restrict__ Bw,
              float* __restrict__ C, int M, int N, int K)
{
    __shared__ __align__(16) float As[8][128];
    __shared__ __align__(16) float Bs[8][128];

    const int tid = threadIdx.x;
    const int tx  = tid & 15;   // N direction (16 * 8 = 128)
    const int ty  = tid >> 4;   // M direction (16 * 8 = 128)
    const int m0  = blockIdx.x * 128;
    const int n0  = blockIdx.y * 128;

    // Each thread loads one float4 from A and one from B per K-block.
    const int lr = tid >> 1;          // 0..127: row within tile
    const int lk = (tid & 1) * 4;     // 0 or 4: k offset (float4)

    int arow = m0 + lr;
    bool avalid = true;
    if (GUARD) {
        avalid = (arow < M);
        if (!avalid) arow = M - 1;    // clamped safe read, contribution zeroed
    }
    const float* Ap = A + (size_t)arow * K + lk;
    const float* Bp = Bw + (size_t)(n0 + lr) * K + lk;

    float4 ar = *(const float4*)Ap;
    if (GUARD && !avalid) ar = make_float4(0.f, 0.f, 0.f, 0.f);
    float4 br = *(const float4*)Bp;

    float acc[8][8];
#pragma unroll
    for (int i = 0; i < 8; ++i)
#pragma unroll
        for (int j = 0; j < 8; ++j) acc[i][j] = 0.f;

    const int nkb = K >> 3;
    for (int kb = 0; kb < nkb; ++kb) {
        // stage current regs into smem (transposed: [k][row])
        As[lk + 0][lr] = ar.x; As[lk + 1][lr] = ar.y;
        As[lk + 2][lr] = ar.z; As[lk + 3][lr] = ar.w;
        Bs[lk + 0][lr] = br.x; Bs[lk + 1][lr] = br.y;
        Bs[lk + 2][lr] = br.z; Bs[lk + 3][lr] = br.w;
        __syncthreads();

        // prefetch next K-block into registers (overlaps with compute)
        if (kb + 1 < nkb) {
            const float* An = Ap + (kb + 1) * 8;
            const float* Bn = Bp + (kb + 1) * 8;
            ar = *(const float4*)An;
            if (GUARD && !avalid) ar = make_float4(0.f, 0.f, 0.f, 0.f);
            br = *(const float4*)Bn;
        }

#pragma unroll
        for (int kk = 0; kk < 8; ++kk) {
            float a[8], b[8];
            *(float4*)&a[0] = *(const float4*)&As[kk][ty * 8];
            *(float4*)&a[4] = *(const float4*)&As[kk][ty * 8 + 4];
            *(float4*)&b[0] = *(const float4*)&Bs[kk][tx * 8];
            *(float4*)&b[4] = *(const float4*)&Bs[kk][tx * 8 + 4];
#pragma unroll
            for (int i = 0; i < 8; ++i)
#pragma unroll
                for (int j = 0; j < 8; ++j)
                    acc[i][j] += a[i] * b[j];
        }
        __syncthreads();
    }

#pragma unroll
    for (int i = 0; i < 8; ++i) {
        const int row = m0 + ty * 8 + i;
        if (GUARD && row >= M) continue;
        float* Cr = C + (size_t)row * N + n0 + tx * 8;
        *(float4*)Cr       = make_float4(acc[i][0], acc[i][1], acc[i][2], acc[i][3]);
        *(float4*)(Cr + 4) = make_float4(acc[i][4], acc[i][5], acc[i][6], acc[i][7]);
    }
}

// ---------------------------------------------------------------------------
// Fused attention: scores + softmax + PV, one warp per query.
// grid: (LQ/64, B_*NH), 256 threads (8 warps), 8 queries per warp.
// K tile in smem with pitch 65 (conflict-free lane-per-j column reads),
// V tile pitch 64 (perfect float2 reads), p broadcast via smem.
// All vector-accessed smem arrays are 16B-aligned (R1 fix: ks has an odd
// float count, which previously left vs on a 4-mod-8 offset -> misaligned
// float2 loads).
// ---------------------------------------------------------------------------
__global__ __launch_bounds__(256)
void attn_kernel(const float* __restrict__ Q, const float* __restrict__ Kc,
                 const float* __restrict__ Vc, float* __restrict__ O)
{
    __shared__ __align__(16) float ks[LK * 65];    // [j][d] pitch 65
    __shared__ __align__(16) float vs[LK * 64];    // [j][d] pitch 64
    __shared__ __align__(16) float qs[8 * 64];     // per-warp query vector
    __shared__ __align__(16) float ps[8 * 80];     // per-warp softmax numerators

    const int tid = threadIdx.x;
    const int w   = tid >> 5;
    const int l   = tid & 31;
    const int bh  = blockIdx.y;
    const int b   = bh >> 3;
    const int h   = bh & 7;

    const float* kg = Kc + (size_t)b * LK * INNER + h * HD;
    const float* vg = Vc + (size_t)b * LK * INNER + h * HD;
    for (int idx = tid; idx < LK * HD; idx += 256) {
        const int j = idx >> 6, d = idx & 63;
        const float kv = kg[(size_t)j * INNER + d];
        const float vv = vg[(size_t)j * INNER + d];
        ks[j * 65 + d] = kv;
        vs[idx]        = vv;
    }
    __syncthreads();

    const float scale = 0.125f;                 // 1/sqrt(64)
    const bool v2 = (l < (LK - 64));            // l < 13
    const int  j2 = v2 ? (l + 64) : 0;          // clamped third j

    for (int qi = 0; qi < 8; ++qi) {
        const int i = blockIdx.x * 64 + qi * 8 + w;
        const float* qrow = Q + ((size_t)(b * LQ + i)) * INNER + h * HD;
        const float2 qv = ((const float2*)qrow)[l];
        qs[w * 64 + 2 * l]     = qv.x * scale;
        qs[w * 64 + 2 * l + 1] = qv.y * scale;
        __syncwarp();

        float s0 = 0.f, s1 = 0.f, s2 = 0.f;
#pragma unroll 8
        for (int d = 0; d < 64; ++d) {
            const float qd = qs[w * 64 + d];
            s0 += qd * ks[l * 65 + d];
            s1 += qd * ks[(l + 32) * 65 + d];
            s2 += qd * ks[j2 * 65 + d];
        }
        if (!v2) s2 = -1e30f;

        float m = fmaxf(s0, fmaxf(s1, s2));
#pragma unroll
        for (int o = 16; o; o >>= 1) m = fmaxf(m, __shfl_xor_sync(0xffffffffu, m, o));

        const float e0 = __expf(s0 - m);
        const float e1 = __expf(s1 - m);
        const float e2 = v2 ? __expf(s2 - m) : 0.f;
        float sum = e0 + e1 + e2;
#pragma unroll
        for (int o = 16; o; o >>= 1) sum += __shfl_xor_sync(0xffffffffu, sum, o);
        const float rs = 1.f / sum;

        ps[w * 80 + l]      = e0;
        ps[w * 80 + l + 32] = e1;
        if (v2) ps[w * 80 + l + 64] = e2;
        __syncwarp();

        float2 acc = make_float2(0.f, 0.f);
#pragma unroll 7
        for (int j = 0; j < LK; ++j) {
            const float pj  = ps[w * 80 + j];
            const float2 vv = ((const float2*)(vs + j * 64))[l];
            acc.x += pj * vv.x;
            acc.y += pj * vv.y;
        }
        acc.x *= rs; acc.y *= rs;

        float* orow = O + ((size_t)(b * LQ + i)) * INNER + h * HD;
        ((float2*)orow)[l] = acc;
        __syncwarp();   // protect qs/ps before next iteration's overwrite
    }
}

// ---------------------------------------------------------------------------
extern "C" void kernel_launch(void* const* d_in, const int* in_sizes, int n_in,
                              void* d_out, int out_size)
{
    (void)in_sizes; (void)n_in; (void)out_size;
    const float* x    = (const float*)d_in[0];
    const float* cond = (const float*)d_in[1];
    const float* w_q  = (const float*)d_in[2];
    const float* w_k  = (const float*)d_in[3];
    const float* w_v  = (const float*)d_in[4];
    const float* w_o  = (const float*)d_in[5];
    float* out = (float*)d_out;

    float *Qb, *Ab, *Kb, *Vb;
    cudaGetSymbolAddress((void**)&Qb, g_Q);
    cudaGetSymbolAddress((void**)&Ab, g_attn);
    cudaGetSymbolAddress((void**)&Kb, g_K);
    cudaGetSymbolAddress((void**)&Vb, g_V);

    const dim3 blk(256);

    // K,V projections: [1232,768] @ [512,768]^T -> [1232,512]
    sgemm_nt<true><<<dim3(10, 4), blk>>>(cond, w_k, Kb, B_ * LK, INNER, DCOND);
    sgemm_nt<true><<<dim3(10, 4), blk>>>(cond, w_v, Vb, B_ * LK, INNER, DCOND);

    // Q projection: [65536,512] @ [512,512]^T -> [65536,512]
    sgemm_nt<false><<<dim3(512, 4), blk>>>(x, w_q, Qb, B_ * LQ, INNER, DMODEL);

    // Fused attention -> g_attn
    attn_kernel<<<dim3(LQ / 64, B_ * NH), blk>>>(Qb, Kb, Vb, Ab);

    // Output projection: [65536,512] @ [512,512]^T -> out
    sgemm_nt<false><<<dim3(512, 4), blk>>>(Ab, w_o, out, B_ * LQ, DMODEL, INNER);
}

// round 4
// speedup vs baseline: 1.8374x; 1.8374x over previous
#include <cuda_runtime.h>
#include <cuda_bf16.h>
#include <cstdint>
#include <math.h>

#define B_     16
#define LQ     4096
#define LK     77
#define DMODEL 512
#define DCOND  768
#define NH     8
#define HD     64
#define INNER  512   // NH*HD

// Scratch (allocation-free rule: __device__ globals)
__device__ float g_Q[(size_t)B_ * LQ * INNER];
__device__ float g_attn[(size_t)B_ * LQ * INNER];
__device__ float g_K[B_ * LK * INNER];
__device__ float g_V[B_ * LK * INNER];

// ===========================================================================
// Helpers (base-PTX only: ldmatrix + mma.sync — no tcgen05 on compute_103)
// ===========================================================================
__device__ __forceinline__ uint32_t smem_u32(const void* p) {
    uint32_t a;
    asm("{ .reg .u64 t; cvta.to.shared.u64 t, %1; cvt.u32.u64 %0, t; }" : "=r"(a) : "l"(p));
    return a;
}
__device__ __forceinline__ uint32_t swz128(uint32_t off) { return off ^ ((off >> 3) & 0x70); }

__device__ __forceinline__ void ldmatrix_x4(uint32_t* r, uint32_t addr) {
    asm volatile("ldmatrix.sync.aligned.m8n8.x4.shared.b16 {%0,%1,%2,%3}, [%4];"
        : "=r"(r[0]), "=r"(r[1]), "=r"(r[2]), "=r"(r[3]) : "r"(addr));
}
__device__ __forceinline__ void ldmatrix_x2(uint32_t* r, uint32_t addr) {
    asm volatile("ldmatrix.sync.aligned.m8n8.x2.shared.b16 {%0,%1}, [%2];"
        : "=r"(r[0]), "=r"(r[1]) : "r"(addr));
}
__device__ __forceinline__ void mma16816(float* d, const uint32_t* a, const uint32_t* b) {
    asm volatile("mma.sync.aligned.m16n8k16.row.col.f32.bf16.bf16.f32 "
        "{%0,%1,%2,%3}, {%4,%5,%6,%7}, {%8,%9}, {%0,%1,%2,%3};"
        : "+f"(d[0]), "+f"(d[1]), "+f"(d[2]), "+f"(d[3])
        : "r"(a[0]), "r"(a[1]), "r"(a[2]), "r"(a[3]), "r"(b[0]), "r"(b[1]));
}

// ===========================================================================
// HMMA GEMM: C[M,512] = A[M,512] @ B[512,512]^T, fp32 in/out.
// bf16 hi/lo split: A·B ≈ Ah·Bh + Ah·Bl + Al·Bh  (rep error ~2^-17).
// 128x128 tile, K-chunk 64, double-buffered smem, 256 thr (8 warps, 2x4),
// warp tile 64x32 (4x4 m16n8k16 tiles). grid = (M/128, 4).
// smem/buffer (64KB): {0:Ah, 16K:Al, 32K:Bh, 48K:Bl}, each 128x64 bf16 SW128.
// ===========================================================================
#define GM_SMEM (2 * 65536)

__global__ void __launch_bounds__(256, 1)
gemm_mma(const float* __restrict__ A, const float* __restrict__ Bw, float* __restrict__ C)
{
    extern __shared__ char sm[];
    const uint32_t base = smem_u32(sm);
    const int tid  = threadIdx.x;
    const int wid  = tid >> 5;
    const int lane = tid & 31;
    const int wm   = wid & 1;    // 2 m-halves (64 rows each)
    const int wn   = wid >> 1;   // 4 n-quarters (32 cols each)

    const int m0 = blockIdx.x * 128;
    const int n0 = blockIdx.y * 128;
    const float* Abase = A + (size_t)m0 * 512;
    const float* Bbase = Bw + (size_t)n0 * 512;

    // loader indices: each thread stages 8 float4 of A and 8 of B per chunk
    const int lrow = tid >> 4;          // 0..15 (x8 rows via i-loop)
    const int lc4  = (tid & 15) * 4;    // k offset within 64 (float4)

    float acc[4][4][4];
#pragma unroll
    for (int mt = 0; mt < 4; ++mt)
#pragma unroll
        for (int nt = 0; nt < 4; ++nt)
#pragma unroll
            for (int q = 0; q < 4; ++q) acc[mt][nt][q] = 0.f;

    // per-lane unswizzled ldmatrix row-base offsets (bytes)
    uint32_t aRow0[4], bRow0[4];
#pragma unroll
    for (int mt = 0; mt < 4; ++mt)
        aRow0[mt] = (uint32_t)((wm * 64 + mt * 16 + (lane & 15)) * 128 + (lane >> 4) * 16);
#pragma unroll
    for (int nt = 0; nt < 4; ++nt)
        bRow0[nt] = (uint32_t)((wn * 32 + nt * 8 + (lane & 7)) * 128 + ((lane >> 3) & 1) * 16);

    auto load_chunk = [&](int c, int buf) {
        char* tb = sm + buf * 65536;
        const int kc = c * 64;
#pragma unroll
        for (int i = 0; i < 8; ++i) {
            const int row = i * 16 + lrow;
            const uint32_t so = swz128((uint32_t)(row * 128 + lc4 * 2));

            float4 av = *(const float4*)(Abase + (size_t)row * 512 + kc + lc4);
            __nv_bfloat16 h0 = __float2bfloat16_rn(av.x), h1 = __float2bfloat16_rn(av.y);
            __nv_bfloat16 h2 = __float2bfloat16_rn(av.z), h3 = __float2bfloat16_rn(av.w);
            uint32_t hi01 = (uint32_t)__bfloat16_as_ushort(h0) | ((uint32_t)__bfloat16_as_ushort(h1) << 16);
            uint32_t hi23 = (uint32_t)__bfloat16_as_ushort(h2) | ((uint32_t)__bfloat16_as_ushort(h3) << 16);
            __nv_bfloat16 l0 = __float2bfloat16_rn(av.x - __bfloat162float(h0));
            __nv_bfloat16 l1 = __float2bfloat16_rn(av.y - __bfloat162float(h1));
            __nv_bfloat16 l2 = __float2bfloat16_rn(av.z - __bfloat162float(h2));
            __nv_bfloat16 l3 = __float2bfloat16_rn(av.w - __bfloat162float(h3));
            uint32_t lo01 = (uint32_t)__bfloat16_as_ushort(l0) | ((uint32_t)__bfloat16_as_ushort(l1) << 16);
            uint32_t lo23 = (uint32_t)__bfloat16_as_ushort(l2) | ((uint32_t)__bfloat16_as_ushort(l3) << 16);
            *(uint2*)(tb + so)         = make_uint2(hi01, hi23);
            *(uint2*)(tb + 16384 + so) = make_uint2(lo01, lo23);

            float4 bv = *(const float4*)(Bbase + (size_t)row * 512 + kc + lc4);
            h0 = __float2bfloat16_rn(bv.x); h1 = __float2bfloat16_rn(bv.y);
            h2 = __float2bfloat16_rn(bv.z); h3 = __float2bfloat16_rn(bv.w);
            hi01 = (uint32_t)__bfloat16_as_ushort(h0) | ((uint32_t)__bfloat16_as_ushort(h1) << 16);
            hi23 = (uint32_t)__bfloat16_as_ushort(h2) | ((uint32_t)__bfloat16_as_ushort(h3) << 16);
            l0 = __float2bfloat16_rn(bv.x - __bfloat162float(h0));
            l1 = __float2bfloat16_rn(bv.y - __bfloat162float(h1));
            l2 = __float2bfloat16_rn(bv.z - __bfloat162float(h2));
            l3 = __float2bfloat16_rn(bv.w - __bfloat162float(h3));
            lo01 = (uint32_t)__bfloat16_as_ushort(l0) | ((uint32_t)__bfloat16_as_ushort(l1) << 16);
            lo23 = (uint32_t)__bfloat16_as_ushort(l2) | ((uint32_t)__bfloat16_as_ushort(l3) << 16);
            *(uint2*)(tb + 32768 + so) = make_uint2(hi01, hi23);
            *(uint2*)(tb + 49152 + so) = make_uint2(lo01, lo23);
        }
    };

    load_chunk(0, 0);
    __syncthreads();

    for (int c = 0; c < 8; ++c) {
        const int buf = c & 1;
        if (c + 1 < 8) load_chunk(c + 1, buf ^ 1);

        const uint32_t bufA = base + buf * 65536;
        const uint32_t bufB = bufA + 32768;

#pragma unroll
        for (int kb = 0; kb < 4; ++kb) {          // 4 k16-steps per chunk
            const uint32_t kbyte = kb * 32;
            uint32_t Ah[4][4], Al[4][4], Bh[4][2], Bl[4][2];
#pragma unroll
            for (int mt = 0; mt < 4; ++mt) {
                const uint32_t off = aRow0[mt] + kbyte;
                const uint32_t so  = off ^ ((off >> 3) & 0x70);
                ldmatrix_x4(Ah[mt], bufA + so);
                ldmatrix_x4(Al[mt], bufA + 16384 + so);
            }
#pragma unroll
            for (int nt = 0; nt < 4; ++nt) {
                const uint32_t off = bRow0[nt] + kbyte;
                const uint32_t so  = off ^ ((off >> 3) & 0x70);
                ldmatrix_x2(Bh[nt], bufB + so);
                ldmatrix_x2(Bl[nt], bufB + 16384 + so);
            }
#pragma unroll
            for (int mt = 0; mt < 4; ++mt)
#pragma unroll
                for (int nt = 0; nt < 4; ++nt)
                    mma16816(acc[mt][nt], Ah[mt], Bh[nt]);
#pragma unroll
            for (int mt = 0; mt < 4; ++mt)
#pragma unroll
                for (int nt = 0; nt < 4; ++nt)
                    mma16816(acc[mt][nt], Ah[mt], Bl[nt]);
#pragma unroll
            for (int mt = 0; mt < 4; ++mt)
#pragma unroll
                for (int nt = 0; nt < 4; ++nt)
                    mma16816(acc[mt][nt], Al[mt], Bh[nt]);
        }
        __syncthreads();
    }

    // Epilogue: D fragment -> global fp32
#pragma unroll
    for (int mt = 0; mt < 4; ++mt) {
        const int r  = m0 + wm * 64 + mt * 16 + (lane >> 2);
#pragma unroll
        for (int nt = 0; nt < 4; ++nt) {
            const int cc = n0 + wn * 32 + nt * 8 + (lane & 3) * 2;
            *(float2*)(C + (size_t)r * 512 + cc)       = make_float2(acc[mt][nt][0], acc[mt][nt][1]);
            *(float2*)(C + (size_t)(r + 8) * 512 + cc) = make_float2(acc[mt][nt][2], acc[mt][nt][3]);
        }
    }
}

// ===========================================================================
// SIMT GEMM (small guarded K/V projections)
// ===========================================================================
template <bool GUARD>
__global__ __launch_bounds__(256, 2)
void sgemm_nt(const float* __restrict__ A, const float* __restrict__ Bw,
              float* __restrict__ C, int M, int N, int K)
{
    __shared__ __align__(16) float As[8][128];
    __shared__ __align__(16) float Bs[8][128];

    const int tid = threadIdx.x;
    const int tx  = tid & 15;
    const int ty  = tid >> 4;
    const int m0  = blockIdx.x * 128;
    const int n0  = blockIdx.y * 128;
    const int lr = tid >> 1;
    const int lk = (tid & 1) * 4;

    int arow = m0 + lr;
    bool avalid = true;
    if (GUARD) { avalid = (arow < M); if (!avalid) arow = M - 1; }
    const float* Ap = A + (size_t)arow * K + lk;
    const float* Bp = Bw + (size_t)(n0 + lr) * K + lk;

    float4 ar = *(const float4*)Ap;
    if (GUARD && !avalid) ar = make_float4(0.f, 0.f, 0.f, 0.f);
    float4 br = *(const float4*)Bp;

    float acc[8][8];
#pragma unroll
    for (int i = 0; i < 8; ++i)
#pragma unroll
        for (int j = 0; j < 8; ++j) acc[i][j] = 0.f;

    const int nkb = K >> 3;
    for (int kb = 0; kb < nkb; ++kb) {
        As[lk + 0][lr] = ar.x; As[lk + 1][lr] = ar.y;
        As[lk + 2][lr] = ar.z; As[lk + 3][lr] = ar.w;
        Bs[lk + 0][lr] = br.x; Bs[lk + 1][lr] = br.y;
        Bs[lk + 2][lr] = br.z; Bs[lk + 3][lr] = br.w;
        __syncthreads();
        if (kb + 1 < nkb) {
            ar = *(const float4*)(Ap + (kb + 1) * 8);
            if (GUARD && !avalid) ar = make_float4(0.f, 0.f, 0.f, 0.f);
            br = *(const float4*)(Bp + (kb + 1) * 8);
        }
#pragma unroll
        for (int kk = 0; kk < 8; ++kk) {
            float a[8], b[8];
            *(float4*)&a[0] = *(const float4*)&As[kk][ty * 8];
            *(float4*)&a[4] = *(const float4*)&As[kk][ty * 8 + 4];
            *(float4*)&b[0] = *(const float4*)&Bs[kk][tx * 8];
            *(float4*)&b[4] = *(const float4*)&Bs[kk][tx * 8 + 4];
#pragma unroll
            for (int i = 0; i < 8; ++i)
#pragma unroll
                for (int j = 0; j < 8; ++j) acc[i][j] += a[i] * b[j];
        }
        __syncthreads();
    }
#pragma unroll
    for (int i = 0; i < 8; ++i) {
        const int row = m0 + ty * 8 + i;
        if (GUARD && row >= M) continue;
        float* Cr = C + (size_t)row * N + n0 + tx * 8;
        *(float4*)Cr       = make_float4(acc[i][0], acc[i][1], acc[i][2], acc[i][3]);
        *(float4*)(Cr + 4) = make_float4(acc[i][4], acc[i][5], acc[i][6], acc[i][7]);
    }
}

// ===========================================================================
// Fused attention, query-batched (8 queries/warp share all K/V smem reads).
// grid (LQ/64, B_*NH), 256 threads. Dynamic smem:
//   ks: 77 x pitch66 fp32, vs: 77 x 64, scr: 8 warps x 640
//   (scr holds q[8][64] during scores, reused as p[8][80] for PV).
// ===========================================================================
#define ATT_VS_OFF 5084
#define ATT_SCR_OFF (ATT_VS_OFF + LK * 64)
#define ATT_SMEM   ((ATT_SCR_OFF + 8 * 640) * 4)

__global__ __launch_bounds__(256)
void attn_kernel(const float* __restrict__ Q, const float* __restrict__ Kc,
                 const float* __restrict__ Vc, float* __restrict__ O)
{
    extern __shared__ float smf[];
    float* ks  = smf;                  // pitch 66
    float* vs  = smf + ATT_VS_OFF;     // pitch 64
    float* scr = smf + ATT_SCR_OFF;    // 640 per warp

    const int tid = threadIdx.x;
    const int w   = tid >> 5;
    const int l   = tid & 31;
    const int bh  = blockIdx.y;
    const int b   = bh >> 3;
    const int h   = bh & 7;

    const float* kg = Kc + (size_t)b * LK * INNER + h * HD;
    const float* vg = Vc + (size_t)b * LK * INNER + h * HD;
    for (int idx = tid; idx < LK * HD; idx += 256) {
        const int j = idx >> 6, d = idx & 63;
        ks[j * 66 + d] = kg[(size_t)j * INNER + d];
        vs[idx]        = vg[(size_t)j * INNER + d];
    }

    float* pw = scr + w * 640;
    const size_t qbase = ((size_t)b * LQ + blockIdx.x * 64 + w * 8) * INNER + h * HD;
#pragma unroll
    for (int qq = 0; qq < 8; ++qq) {
        const float2 qv = ((const float2*)(Q + qbase + (size_t)qq * INNER))[l];
        pw[qq * 80 + 2 * l]     = qv.x * 0.125f;
        pw[qq * 80 + 2 * l + 1] = qv.y * 0.125f;
    }
    __syncthreads();

    // ---- scores: lane owns keys l, l+32, (64+l if l<13), all 8 queries ----
    const bool v2 = (l < (LK - 64));
    const int  j2 = v2 ? (64 + l) : 64;
    float s0[8], s1[8], s2[8];
#pragma unroll
    for (int qq = 0; qq < 8; ++qq) { s0[qq] = 0.f; s1[qq] = 0.f; s2[qq] = 0.f; }

    for (int d = 0; d < 64; d += 2) {
        const float2 k0 = *(const float2*)(ks + l * 66 + d);
        const float2 k1 = *(const float2*)(ks + (l + 32) * 66 + d);
        const float2 k2 = *(const float2*)(ks + j2 * 66 + d);
#pragma unroll
        for (int qq = 0; qq < 8; ++qq) {
            const float2 qv = *(const float2*)(pw + qq * 80 + d);
            s0[qq] += qv.x * k0.x + qv.y * k0.y;
            s1[qq] += qv.x * k1.x + qv.y * k1.y;
            s2[qq] += qv.x * k2.x + qv.y * k2.y;
        }
    }
    __syncwarp();

    // ---- softmax per query; p overwrites q region ----
    float rs[8];
#pragma unroll
    for (int qq = 0; qq < 8; ++qq) {
        float a0 = s0[qq], a1 = s1[qq];
        float a2 = v2 ? s2[qq] : -1e30f;
        float m = fmaxf(a0, fmaxf(a1, a2));
#pragma unroll
        for (int o = 16; o; o >>= 1) m = fmaxf(m, __shfl_xor_sync(0xffffffffu, m, o));
        const float e0 = __expf(a0 - m);
        const float e1 = __expf(a1 - m);
        const float e2 = v2 ? __expf(a2 - m) : 0.f;
        float sum = e0 + e1 + e2;
#pragma unroll
        for (int o = 16; o; o >>= 1) sum += __shfl_xor_sync(0xffffffffu, sum, o);
        rs[qq] = 1.f / sum;
        pw[qq * 80 + l]      = e0;
        pw[qq * 80 + l + 32] = e1;
        if (v2) pw[qq * 80 + 64 + l] = e2;
    }
    __syncwarp();

    // ---- PV: lane owns out cols 2l, 2l+1 for all 8 queries ----
    float2 acc[8];
#pragma unroll
    for (int qq = 0; qq < 8; ++qq) acc[qq] = make_float2(0.f, 0.f);

    for (int jp = 0; jp < 76; jp += 2) {
        const float2 v0 = *(const float2*)(vs + jp * 64 + 2 * l);
        const float2 v1 = *(const float2*)(vs + (jp + 1) * 64 + 2 * l);
#pragma unroll
        for (int qq = 0; qq < 8; ++qq) {
            const float2 p2 = *(const float2*)(pw + qq * 80 + jp);
            acc[qq].x += p2.x * v0.x + p2.y * v1.x;
            acc[qq].y += p2.x * v0.y + p2.y * v1.y;
        }
    }
    {   // remainder j = 76
        const float2 v0 = *(const float2*)(vs + 76 * 64 + 2 * l);
#pragma unroll
        for (int qq = 0; qq < 8; ++qq) {
            const float pj = pw[qq * 80 + 76];
            acc[qq].x += pj * v0.x;
            acc[qq].y += pj * v0.y;
        }
    }

#pragma unroll
    for (int qq = 0; qq < 8; ++qq) {
        float2 o = make_float2(acc[qq].x * rs[qq], acc[qq].y * rs[qq]);
        ((float2*)(O + qbase + (size_t)qq * INNER))[l] = o;
    }
}

// ===========================================================================
extern "C" void kernel_launch(void* const* d_in, const int* in_sizes, int n_in,
                              void* d_out, int out_size)
{
    (void)in_sizes; (void)n_in; (void)out_size;
    const float* x    = (const float*)d_in[0];
    const float* cond = (const float*)d_in[1];
    const float* w_q  = (const float*)d_in[2];
    const float* w_k  = (const float*)d_in[3];
    const float* w_v  = (const float*)d_in[4];
    const float* w_o  = (const float*)d_in[5];
    float* out = (float*)d_out;

    float *Qb, *Ab, *Kb, *Vb;
    cudaGetSymbolAddress((void**)&Qb, g_Q);
    cudaGetSymbolAddress((void**)&Ab, g_attn);
    cudaGetSymbolAddress((void**)&Kb, g_K);
    cudaGetSymbolAddress((void**)&Vb, g_V);

    cudaFuncSetAttribute(gemm_mma, cudaFuncAttributeMaxDynamicSharedMemorySize, GM_SMEM);
    cudaFuncSetAttribute(attn_kernel, cudaFuncAttributeMaxDynamicSharedMemorySize, ATT_SMEM);

    // K,V projections (small, guarded SIMT): [1232,768] @ [512,768]^T
    sgemm_nt<true><<<dim3(10, 4), 256>>>(cond, w_k, Kb, B_ * LK, INNER, DCOND);
    sgemm_nt<true><<<dim3(10, 4), 256>>>(cond, w_v, Vb, B_ * LK, INNER, DCOND);

    // Q projection (HMMA bf16-split): [65536,512] @ [512,512]^T
    gemm_mma<<<dim3(512, 4), 256, GM_SMEM>>>(x, w_q, Qb);

    // Fused attention
    attn_kernel<<<dim3(LQ / 64, B_ * NH), 256, ATT_SMEM>>>(Qb, Kb, Vb, Ab);

    // Output projection (HMMA bf16-split): [65536,512] @ [512,512]^T
    gemm_mma<<<dim3(512, 4), 256, GM_SMEM>>>(Ab, w_o, out);
}

// round 5
// speedup vs baseline: 2.2166x; 1.2063x over previous
#include <cuda_runtime.h>
#include <cuda_bf16.h>
#include <cstdint>
#include <math.h>

#define B_     16
#define LQ     4096
#define LK     77
#define DMODEL 512
#define DCOND  768
#define NH     8
#define HD     64
#define INNER  512   // NH*HD

// Scratch (allocation-free rule: __device__ globals)
__device__ float g_Q[(size_t)B_ * LQ * INNER];                 // 128 MB
__device__ __nv_bfloat16 g_xhi[(size_t)B_ * LQ * DMODEL];      // 64 MB
__device__ __nv_bfloat16 g_xlo[(size_t)B_ * LQ * DMODEL];
__device__ __nv_bfloat16 g_ahi[(size_t)B_ * LQ * INNER];
__device__ __nv_bfloat16 g_alo[(size_t)B_ * LQ * INNER];
__device__ __nv_bfloat16 g_wqhi[DMODEL * INNER];
__device__ __nv_bfloat16 g_wqlo[DMODEL * INNER];
__device__ __nv_bfloat16 g_wohi[DMODEL * INNER];
__device__ __nv_bfloat16 g_wolo[DMODEL * INNER];
__device__ float g_K[B_ * LK * INNER];
__device__ float g_V[B_ * LK * INNER];

// ===========================================================================
// Helpers (base PTX only)
// ===========================================================================
__device__ __forceinline__ uint32_t smem_u32(const void* p) {
    uint32_t a;
    asm("{ .reg .u64 t; cvta.to.shared.u64 t, %1; cvt.u32.u64 %0, t; }" : "=r"(a) : "l"(p));
    return a;
}
__device__ __forceinline__ uint32_t swz128(uint32_t off) { return off ^ ((off >> 3) & 0x70); }

__device__ __forceinline__ void ldmatrix_x4(uint32_t* r, uint32_t addr) {
    asm volatile("ldmatrix.sync.aligned.m8n8.x4.shared.b16 {%0,%1,%2,%3}, [%4];"
        : "=r"(r[0]), "=r"(r[1]), "=r"(r[2]), "=r"(r[3]) : "r"(addr));
}
__device__ __forceinline__ void ldmatrix_x2(uint32_t* r, uint32_t addr) {
    asm volatile("ldmatrix.sync.aligned.m8n8.x2.shared.b16 {%0,%1}, [%2];"
        : "=r"(r[0]), "=r"(r[1]) : "r"(addr));
}
__device__ __forceinline__ void mma16816(float* d, const uint32_t* a, const uint32_t* b) {
    asm volatile("mma.sync.aligned.m16n8k16.row.col.f32.bf16.bf16.f32 "
        "{%0,%1,%2,%3}, {%4,%5,%6,%7}, {%8,%9}, {%0,%1,%2,%3};"
        : "+f"(d[0]), "+f"(d[1]), "+f"(d[2]), "+f"(d[3])
        : "r"(a[0]), "r"(a[1]), "r"(a[2]), "r"(a[3]), "r"(b[0]), "r"(b[1]));
}
__device__ __forceinline__ void cp_async16(uint32_t dst, const void* src) {
    asm volatile("cp.async.cg.shared.global [%0], [%1], 16;" :: "r"(dst), "l"(src));
}
#define CP_COMMIT() asm volatile("cp.async.commit_group;" ::: "memory")
#define CP_WAIT1()  asm volatile("cp.async.wait_group 1;" ::: "memory")

// packed fp32x2 (Blackwell FFMA2)
__device__ __forceinline__ void fma2(uint64_t& d, uint64_t a, uint64_t b) {
    asm("fma.rn.f32x2 %0, %1, %2, %0;" : "+l"(d) : "l"(a), "l"(b));
}
__device__ __forceinline__ float hadd2(uint64_t v) {
    float lo, hi;
    asm("mov.b64 {%0,%1}, %2;" : "=f"(lo), "=f"(hi) : "l"(v));
    return lo + hi;
}

// split one float into bf16 hi + lo residual, packed pairwise
__device__ __forceinline__ void split4(float4 v, uint32_t& hi01, uint32_t& hi23,
                                       uint32_t& lo01, uint32_t& lo23) {
    __nv_bfloat16 h0 = __float2bfloat16_rn(v.x), h1 = __float2bfloat16_rn(v.y);
    __nv_bfloat16 h2 = __float2bfloat16_rn(v.z), h3 = __float2bfloat16_rn(v.w);
    hi01 = (uint32_t)__bfloat16_as_ushort(h0) | ((uint32_t)__bfloat16_as_ushort(h1) << 16);
    hi23 = (uint32_t)__bfloat16_as_ushort(h2) | ((uint32_t)__bfloat16_as_ushort(h3) << 16);
    __nv_bfloat16 l0 = __float2bfloat16_rn(v.x - __bfloat162float(h0));
    __nv_bfloat16 l1 = __float2bfloat16_rn(v.y - __bfloat162float(h1));
    __nv_bfloat16 l2 = __float2bfloat16_rn(v.z - __bfloat162float(h2));
    __nv_bfloat16 l3 = __float2bfloat16_rn(v.w - __bfloat162float(h3));
    lo01 = (uint32_t)__bfloat16_as_ushort(l0) | ((uint32_t)__bfloat16_as_ushort(l1) << 16);
    lo23 = (uint32_t)__bfloat16_as_ushort(l2) | ((uint32_t)__bfloat16_as_ushort(l3) << 16);
}

// ===========================================================================
// fp32 -> bf16 hi/lo split (memory-bound preprocessing)
// ===========================================================================
__global__ void cvt_split(const float4* __restrict__ in, uint2* __restrict__ hi,
                          uint2* __restrict__ lo, int n4)
{
    const int i = blockIdx.x * blockDim.x + threadIdx.x;
    if (i >= n4) return;
    uint32_t h01, h23, l01, l23;
    split4(in[i], h01, h23, l01, l23);
    hi[i] = make_uint2(h01, h23);
    lo[i] = make_uint2(l01, l23);
}

// ===========================================================================
// HMMA GEMM on pre-split bf16: C[M,512] = A[M,512] @ B[512,512]^T  (fp32 C)
// A ~ Ah+Al, B ~ Bh+Bl; C = Ah·Bh + Ah·Bl + Al·Bh.
// 128x128 tile, K-chunk 64, cp.async double buffer, 256 thr (8 warps 2x4),
// warp tile 64x32. grid (M/128, 4).
// smem/buffer 64KB: {0:Ah, 16K:Al, 32K:Bh, 48K:Bl}, each 128x64 bf16 SW128.
// ===========================================================================
#define GM_SMEM (2 * 65536)

__global__ void __launch_bounds__(256, 1)
gemm_bf16(const __nv_bfloat16* __restrict__ Ah, const __nv_bfloat16* __restrict__ Al,
          const __nv_bfloat16* __restrict__ Bh, const __nv_bfloat16* __restrict__ Bl,
          float* __restrict__ C)
{
    extern __shared__ char sm[];
    const uint32_t base = smem_u32(sm);
    const int tid  = threadIdx.x;
    const int wid  = tid >> 5;
    const int lane = tid & 31;
    const int wm   = wid & 1;
    const int wn   = wid >> 1;

    const int m0 = blockIdx.x * 128;
    const int n0 = blockIdx.y * 128;
    const __nv_bfloat16* Ah0 = Ah + (size_t)m0 * 512;
    const __nv_bfloat16* Al0 = Al + (size_t)m0 * 512;
    const __nv_bfloat16* Bh0 = Bh + (size_t)n0 * 512;
    const __nv_bfloat16* Bl0 = Bl + (size_t)n0 * 512;

    float acc[4][4][4];
#pragma unroll
    for (int mt = 0; mt < 4; ++mt)
#pragma unroll
        for (int nt = 0; nt < 4; ++nt)
#pragma unroll
            for (int q = 0; q < 4; ++q) acc[mt][nt][q] = 0.f;

    uint32_t aRow0[4], bRow0[4];
#pragma unroll
    for (int mt = 0; mt < 4; ++mt)
        aRow0[mt] = (uint32_t)((wm * 64 + mt * 16 + (lane & 15)) * 128 + (lane >> 4) * 16);
#pragma unroll
    for (int nt = 0; nt < 4; ++nt)
        bRow0[nt] = (uint32_t)((wn * 32 + nt * 8 + (lane & 7)) * 128 + ((lane >> 3) & 1) * 16);

    // per-chunk async stage: 4 tiles x 1024 x 16B, 16 cp.async per thread
    auto issue_chunk = [&](int c, int buf) {
        const int kc = c * 64;
        const uint32_t tb = base + buf * 65536;
#pragma unroll
        for (int i = 0; i < 4; ++i) {
            const int idx  = i * 256 + tid;      // 0..1023
            const int row  = idx >> 3;
            const int c16  = idx & 7;
            const uint32_t so = swz128((uint32_t)(row * 128 + c16 * 16));
            const size_t go = (size_t)row * 512 + kc + c16 * 8;
            cp_async16(tb + so,         Ah0 + go);
            cp_async16(tb + 16384 + so, Al0 + go);
            cp_async16(tb + 32768 + so, Bh0 + go);
            cp_async16(tb + 49152 + so, Bl0 + go);
        }
    };

    issue_chunk(0, 0); CP_COMMIT();
    issue_chunk(1, 1); CP_COMMIT();

    for (int c = 0; c < 8; ++c) {
        const int buf = c & 1;
        CP_WAIT1();
        __syncthreads();

        const uint32_t bufA = base + buf * 65536;
        const uint32_t bufB = bufA + 32768;
#pragma unroll
        for (int kb = 0; kb < 4; ++kb) {
            const uint32_t kbyte = kb * 32;
            uint32_t Ahf[4][4], Alf[4][4], Bhf[4][2], Blf[4][2];
#pragma unroll
            for (int mt = 0; mt < 4; ++mt) {
                const uint32_t off = aRow0[mt] + kbyte;
                const uint32_t so  = off ^ ((off >> 3) & 0x70);
                ldmatrix_x4(Ahf[mt], bufA + so);
                ldmatrix_x4(Alf[mt], bufA + 16384 + so);
            }
#pragma unroll
            for (int nt = 0; nt < 4; ++nt) {
                const uint32_t off = bRow0[nt] + kbyte;
                const uint32_t so  = off ^ ((off >> 3) & 0x70);
                ldmatrix_x2(Bhf[nt], bufB + so);
                ldmatrix_x2(Blf[nt], bufB + 16384 + so);
            }
#pragma unroll
            for (int mt = 0; mt < 4; ++mt)
#pragma unroll
                for (int nt = 0; nt < 4; ++nt)
                    mma16816(acc[mt][nt], Ahf[mt], Bhf[nt]);
#pragma unroll
            for (int mt = 0; mt < 4; ++mt)
#pragma unroll
                for (int nt = 0; nt < 4; ++nt)
                    mma16816(acc[mt][nt], Ahf[mt], Blf[nt]);
#pragma unroll
            for (int mt = 0; mt < 4; ++mt)
#pragma unroll
                for (int nt = 0; nt < 4; ++nt)
                    mma16816(acc[mt][nt], Alf[mt], Bhf[nt]);
        }
        __syncthreads();
        if (c + 2 < 8) issue_chunk(c + 2, buf);
        CP_COMMIT();
    }

    // Epilogue
#pragma unroll
    for (int mt = 0; mt < 4; ++mt) {
        const int r = m0 + wm * 64 + mt * 16 + (lane >> 2);
#pragma unroll
        for (int nt = 0; nt < 4; ++nt) {
            const int cc = n0 + wn * 32 + nt * 8 + (lane & 3) * 2;
            *(float2*)(C + (size_t)r * 512 + cc)       = make_float2(acc[mt][nt][0], acc[mt][nt][1]);
            *(float2*)(C + (size_t)(r + 8) * 512 + cc) = make_float2(acc[mt][nt][2], acc[mt][nt][3]);
        }
    }
}

// ===========================================================================
// SIMT GEMM (small guarded K/V projections)
// ===========================================================================
template <bool GUARD>
__global__ __launch_bounds__(256, 2)
void sgemm_nt(const float* __restrict__ A, const float* __restrict__ Bw,
              float* __restrict__ C, int M, int N, int K)
{
    __shared__ __align__(16) float As[8][128];
    __shared__ __align__(16) float Bs[8][128];

    const int tid = threadIdx.x;
    const int tx  = tid & 15;
    const int ty  = tid >> 4;
    const int m0  = blockIdx.x * 128;
    const int n0  = blockIdx.y * 128;
    const int lr = tid >> 1;
    const int lk = (tid & 1) * 4;

    int arow = m0 + lr;
    bool avalid = true;
    if (GUARD) { avalid = (arow < M); if (!avalid) arow = M - 1; }
    const float* Ap = A + (size_t)arow * K + lk;
    const float* Bp = Bw + (size_t)(n0 + lr) * K + lk;

    float4 ar = *(const float4*)Ap;
    if (GUARD && !avalid) ar = make_float4(0.f, 0.f, 0.f, 0.f);
    float4 br = *(const float4*)Bp;

    float acc[8][8];
#pragma unroll
    for (int i = 0; i < 8; ++i)
#pragma unroll
        for (int j = 0; j < 8; ++j) acc[i][j] = 0.f;

    const int nkb = K >> 3;
    for (int kb = 0; kb < nkb; ++kb) {
        As[lk + 0][lr] = ar.x; As[lk + 1][lr] = ar.y;
        As[lk + 2][lr] = ar.z; As[lk + 3][lr] = ar.w;
        Bs[lk + 0][lr] = br.x; Bs[lk + 1][lr] = br.y;
        Bs[lk + 2][lr] = br.z; Bs[lk + 3][lr] = br.w;
        __syncthreads();
        if (kb + 1 < nkb) {
            ar = *(const float4*)(Ap + (kb + 1) * 8);
            if (GUARD && !avalid) ar = make_float4(0.f, 0.f, 0.f, 0.f);
            br = *(const float4*)(Bp + (kb + 1) * 8);
        }
#pragma unroll
        for (int kk = 0; kk < 8; ++kk) {
            float a[8], b[8];
            *(float4*)&a[0] = *(const float4*)&As[kk][ty * 8];
            *(float4*)&a[4] = *(const float4*)&As[kk][ty * 8 + 4];
            *(float4*)&b[0] = *(const float4*)&Bs[kk][tx * 8];
            *(float4*)&b[4] = *(const float4*)&Bs[kk][tx * 8 + 4];
#pragma unroll
            for (int i = 0; i < 8; ++i)
#pragma unroll
                for (int j = 0; j < 8; ++j) acc[i][j] += a[i] * b[j];
        }
        __syncthreads();
    }
#pragma unroll
    for (int i = 0; i < 8; ++i) {
        const int row = m0 + ty * 8 + i;
        if (GUARD && row >= M) continue;
        float* Cr = C + (size_t)row * N + n0 + tx * 8;
        *(float4*)Cr       = make_float4(acc[i][0], acc[i][1], acc[i][2], acc[i][3]);
        *(float4*)(Cr + 4) = make_float4(acc[i][4], acc[i][5], acc[i][6], acc[i][7]);
    }
}

// ===========================================================================
// Fused attention, query-batched + packed f32x2 FMA.
// grid (LQ/64, B_*NH), 256 threads. Outputs bf16 hi/lo (feeds the O-proj GEMM).
// smem: ks[77][66] fp32, vt[64][82] fp32 (V transposed), scr 8w x 640.
// ===========================================================================
#define KS_PITCH 66
#define VT_PITCH 82
#define ATT_VT_OFF  5084                       // 77*66=5082, +2 pad (8B align)
#define ATT_SCR_OFF (ATT_VT_OFF + 64 * VT_PITCH)   // 5084+5248=10332
#define ATT_SMEM    ((ATT_SCR_OFF + 8 * 640) * 4)  // 61808 B

__global__ __launch_bounds__(256)
void attn_kernel(const float* __restrict__ Q, const float* __restrict__ Kc,
                 const float* __restrict__ Vc,
                 __nv_bfloat16* __restrict__ Ohi, __nv_bfloat16* __restrict__ Olo)
{
    extern __shared__ float smf[];
    float* ks  = smf;                  // [j][d] pitch 66
    float* vt  = smf + ATT_VT_OFF;     // [d][j] pitch 82 (transposed V)
    float* scr = smf + ATT_SCR_OFF;

    const int tid = threadIdx.x;
    const int w   = tid >> 5;
    const int l   = tid & 31;
    const int bh  = blockIdx.y;
    const int b   = bh >> 3;
    const int h   = bh & 7;

    const float* kg = Kc + (size_t)b * LK * INNER + h * HD;
    const float* vg = Vc + (size_t)b * LK * INNER + h * HD;
    for (int idx = tid; idx < LK * HD; idx += 256) {
        const int j = idx >> 6, d = idx & 63;
        ks[j * KS_PITCH + d] = kg[(size_t)j * INNER + d];
        vt[d * VT_PITCH + j] = vg[(size_t)j * INNER + d];
    }

    float* pw = scr + w * 640;
    const size_t qbase = ((size_t)b * LQ + blockIdx.x * 64 + w * 8) * INNER + h * HD;
#pragma unroll
    for (int qq = 0; qq < 8; ++qq) {
        const float2 qv = ((const float2*)(Q + qbase + (size_t)qq * INNER))[l];
        pw[qq * 80 + 2 * l]     = qv.x * 0.125f;
        pw[qq * 80 + 2 * l + 1] = qv.y * 0.125f;
    }
    __syncthreads();

    // ---- scores (packed over d): lane owns keys l, l+32, (64+l | l<13) ----
    const bool v2 = (l < (LK - 64));
    const int  j2 = v2 ? (64 + l) : 64;
    uint64_t a0[8], a1[8], a2[8];
#pragma unroll
    for (int qq = 0; qq < 8; ++qq) { a0[qq] = 0; a1[qq] = 0; a2[qq] = 0; }

#pragma unroll 4
    for (int d = 0; d < 64; d += 2) {
        const uint64_t k0 = *(const uint64_t*)(ks + l * KS_PITCH + d);
        const uint64_t k1 = *(const uint64_t*)(ks + (l + 32) * KS_PITCH + d);
        const uint64_t k2 = *(const uint64_t*)(ks + j2 * KS_PITCH + d);
#pragma unroll
        for (int qq = 0; qq < 8; ++qq) {
            const uint64_t q2 = *(const uint64_t*)(pw + qq * 80 + d);
            fma2(a0[qq], q2, k0);
            fma2(a1[qq], q2, k1);
            fma2(a2[qq], q2, k2);
        }
    }
    __syncwarp();

    // ---- softmax per query; p overwrites q region ----
    float rs[8];
#pragma unroll
    for (int qq = 0; qq < 8; ++qq) {
        const float s0 = hadd2(a0[qq]);
        const float s1 = hadd2(a1[qq]);
        const float s2v = hadd2(a2[qq]);
        const float s2 = v2 ? s2v : -1e30f;
        float m = fmaxf(s0, fmaxf(s1, s2));
#pragma unroll
        for (int o = 16; o; o >>= 1) m = fmaxf(m, __shfl_xor_sync(0xffffffffu, m, o));
        const float e0 = __expf(s0 - m);
        const float e1 = __expf(s1 - m);
        const float e2 = v2 ? __expf(s2 - m) : 0.f;
        float sum = e0 + e1 + e2;
#pragma unroll
        for (int o = 16; o; o >>= 1) sum += __shfl_xor_sync(0xffffffffu, sum, o);
        rs[qq] = 1.f / sum;
        pw[qq * 80 + l]      = e0;
        pw[qq * 80 + l + 32] = e1;
        if (v2) pw[qq * 80 + 64 + l] = e2;
    }
    __syncwarp();

    // ---- PV (packed over j, V transposed): lane owns out dims 2l, 2l+1 ----
    uint64_t px[8], py[8];
#pragma unroll
    for (int qq = 0; qq < 8; ++qq) { px[qq] = 0; py[qq] = 0; }

    const float* vr0 = vt + (2 * l) * VT_PITCH;
    const float* vr1 = vt + (2 * l + 1) * VT_PITCH;
#pragma unroll 2
    for (int jp = 0; jp < 76; jp += 2) {
        const uint64_t v0 = *(const uint64_t*)(vr0 + jp);
        const uint64_t v1 = *(const uint64_t*)(vr1 + jp);
#pragma unroll
        for (int qq = 0; qq < 8; ++qq) {
            const uint64_t p2 = *(const uint64_t*)(pw + qq * 80 + jp);
            fma2(px[qq], p2, v0);
            fma2(py[qq], p2, v1);
        }
    }
    const float v0r = vr0[76];
    const float v1r = vr1[76];

#pragma unroll
    for (int qq = 0; qq < 8; ++qq) {
        const float pr = pw[qq * 80 + 76];
        const float ox = (hadd2(px[qq]) + pr * v0r) * rs[qq];
        const float oy = (hadd2(py[qq]) + pr * v1r) * rs[qq];
        const __nv_bfloat16 hx = __float2bfloat16_rn(ox);
        const __nv_bfloat16 hy = __float2bfloat16_rn(oy);
        const __nv_bfloat16 lx = __float2bfloat16_rn(ox - __bfloat162float(hx));
        const __nv_bfloat16 ly = __float2bfloat16_rn(oy - __bfloat162float(hy));
        __nv_bfloat162 hv; hv.x = hx; hv.y = hy;
        __nv_bfloat162 lv; lv.x = lx; lv.y = ly;
        ((__nv_bfloat162*)(Ohi + qbase + (size_t)qq * INNER))[l] = hv;
        ((__nv_bfloat162*)(Olo + qbase + (size_t)qq * INNER))[l] = lv;
    }
}

// ===========================================================================
extern "C" void kernel_launch(void* const* d_in, const int* in_sizes, int n_in,
                              void* d_out, int out_size)
{
    (void)in_sizes; (void)n_in; (void)out_size;
    const float* x    = (const float*)d_in[0];
    const float* cond = (const float*)d_in[1];
    const float* w_q  = (const float*)d_in[2];
    const float* w_k  = (const float*)d_in[3];
    const float* w_v  = (const float*)d_in[4];
    const float* w_o  = (const float*)d_in[5];
    float* out = (float*)d_out;

    float *Qb, *Kb, *Vb;
    __nv_bfloat16 *xhi, *xlo, *ahi, *alo, *wqhi, *wqlo, *wohi, *wolo;
    cudaGetSymbolAddress((void**)&Qb, g_Q);
    cudaGetSymbolAddress((void**)&Kb, g_K);
    cudaGetSymbolAddress((void**)&Vb, g_V);
    cudaGetSymbolAddress((void**)&xhi, g_xhi);
    cudaGetSymbolAddress((void**)&xlo, g_xlo);
    cudaGetSymbolAddress((void**)&ahi, g_ahi);
    cudaGetSymbolAddress((void**)&alo, g_alo);
    cudaGetSymbolAddress((void**)&wqhi, g_wqhi);
    cudaGetSymbolAddress((void**)&wqlo, g_wqlo);
    cudaGetSymbolAddress((void**)&wohi, g_wohi);
    cudaGetSymbolAddress((void**)&wolo, g_wolo);

    cudaFuncSetAttribute(gemm_bf16, cudaFuncAttributeMaxDynamicSharedMemorySize, GM_SMEM);
    cudaFuncSetAttribute(attn_kernel, cudaFuncAttributeMaxDynamicSharedMemorySize, ATT_SMEM);

    // Pre-split to bf16 hi/lo (memory-bound)
    const int XN4 = B_ * LQ * DMODEL / 4;      // 8.4M float4
    const int WN4 = DMODEL * INNER / 4;        // 64K float4
    cvt_split<<<(XN4 + 255) / 256, 256>>>((const float4*)x, (uint2*)xhi, (uint2*)xlo, XN4);
    cvt_split<<<(WN4 + 255) / 256, 256>>>((const float4*)w_q, (uint2*)wqhi, (uint2*)wqlo, WN4);
    cvt_split<<<(WN4 + 255) / 256, 256>>>((const float4*)w_o, (uint2*)wohi, (uint2*)wolo, WN4);

    // K,V projections (fp32 SIMT, small): [1232,768] @ [512,768]^T
    sgemm_nt<true><<<dim3(10, 4), 256>>>(cond, w_k, Kb, B_ * LK, INNER, DCOND);
    sgemm_nt<true><<<dim3(10, 4), 256>>>(cond, w_v, Vb, B_ * LK, INNER, DCOND);

    // Q projection (tensor cores, pre-split operands)
    gemm_bf16<<<dim3(512, 4), 256, GM_SMEM>>>(xhi, xlo, wqhi, wqlo, Qb);

    // Fused attention -> bf16 hi/lo
    attn_kernel<<<dim3(LQ / 64, B_ * NH), 256, ATT_SMEM>>>(Qb, Kb, Vb, ahi, alo);

    // Output projection
    gemm_bf16<<<dim3(512, 4), 256, GM_SMEM>>>(ahi, alo, wohi, wolo, out);
}

// round 6
// speedup vs baseline: 2.4444x; 1.1028x over previous
#include <cuda_runtime.h>
#include <cuda_bf16.h>
#include <cstdint>
#include <math.h>

#define B_     16
#define LQ     4096
#define LK     77
#define DMODEL 512
#define DCOND  768
#define NH     8
#define HD     64
#define INNER  512   // NH*HD

// Scratch (allocation-free rule: __device__ globals)
__device__ float g_Q[(size_t)B_ * LQ * INNER];                 // 128 MB
__device__ __nv_bfloat16 g_xhi[(size_t)B_ * LQ * DMODEL];
__device__ __nv_bfloat16 g_xlo[(size_t)B_ * LQ * DMODEL];
__device__ __nv_bfloat16 g_ahi[(size_t)B_ * LQ * INNER];
__device__ __nv_bfloat16 g_alo[(size_t)B_ * LQ * INNER];
__device__ __nv_bfloat16 g_wqhi[DMODEL * INNER];
__device__ __nv_bfloat16 g_wqlo[DMODEL * INNER];
__device__ __nv_bfloat16 g_wohi[DMODEL * INNER];
__device__ __nv_bfloat16 g_wolo[DMODEL * INNER];
__device__ float g_K[B_ * LK * INNER];
__device__ float g_V[B_ * LK * INNER];

// ===========================================================================
// Helpers (base PTX only)
// ===========================================================================
__device__ __forceinline__ uint32_t smem_u32(const void* p) {
    uint32_t a;
    asm("{ .reg .u64 t; cvta.to.shared.u64 t, %1; cvt.u32.u64 %0, t; }" : "=r"(a) : "l"(p));
    return a;
}
__device__ __forceinline__ uint32_t swz128(uint32_t off) { return off ^ ((off >> 3) & 0x70); }

__device__ __forceinline__ void ldmatrix_x4(uint32_t* r, uint32_t addr) {
    asm volatile("ldmatrix.sync.aligned.m8n8.x4.shared.b16 {%0,%1,%2,%3}, [%4];"
        : "=r"(r[0]), "=r"(r[1]), "=r"(r[2]), "=r"(r[3]) : "r"(addr));
}
__device__ __forceinline__ void ldmatrix_x2(uint32_t* r, uint32_t addr) {
    asm volatile("ldmatrix.sync.aligned.m8n8.x2.shared.b16 {%0,%1}, [%2];"
        : "=r"(r[0]), "=r"(r[1]) : "r"(addr));
}
__device__ __forceinline__ void mma16816(float* d, const uint32_t* a, const uint32_t* b) {
    asm volatile("mma.sync.aligned.m16n8k16.row.col.f32.bf16.bf16.f32 "
        "{%0,%1,%2,%3}, {%4,%5,%6,%7}, {%8,%9}, {%0,%1,%2,%3};"
        : "+f"(d[0]), "+f"(d[1]), "+f"(d[2]), "+f"(d[3])
        : "r"(a[0]), "r"(a[1]), "r"(a[2]), "r"(a[3]), "r"(b[0]), "r"(b[1]));
}
__device__ __forceinline__ void cp_async16(uint32_t dst, const void* src) {
    asm volatile("cp.async.cg.shared.global [%0], [%1], 16;" :: "r"(dst), "l"(src));
}
#define CP_COMMIT() asm volatile("cp.async.commit_group;" ::: "memory")
#define CP_WAIT2()  asm volatile("cp.async.wait_group 2;" ::: "memory")

// packed fp32x2 (Blackwell FFMA2)
__device__ __forceinline__ void fma2(uint64_t& d, uint64_t a, uint64_t b) {
    asm("fma.rn.f32x2 %0, %1, %2, %0;" : "+l"(d) : "l"(a), "l"(b));
}
__device__ __forceinline__ float hadd2(uint64_t v) {
    float lo, hi;
    asm("mov.b64 {%0,%1}, %2;" : "=f"(lo), "=f"(hi) : "l"(v));
    return lo + hi;
}

__device__ __forceinline__ void split4(float4 v, uint32_t& hi01, uint32_t& hi23,
                                       uint32_t& lo01, uint32_t& lo23) {
    __nv_bfloat16 h0 = __float2bfloat16_rn(v.x), h1 = __float2bfloat16_rn(v.y);
    __nv_bfloat16 h2 = __float2bfloat16_rn(v.z), h3 = __float2bfloat16_rn(v.w);
    hi01 = (uint32_t)__bfloat16_as_ushort(h0) | ((uint32_t)__bfloat16_as_ushort(h1) << 16);
    hi23 = (uint32_t)__bfloat16_as_ushort(h2) | ((uint32_t)__bfloat16_as_ushort(h3) << 16);
    __nv_bfloat16 l0 = __float2bfloat16_rn(v.x - __bfloat162float(h0));
    __nv_bfloat16 l1 = __float2bfloat16_rn(v.y - __bfloat162float(h1));
    __nv_bfloat16 l2 = __float2bfloat16_rn(v.z - __bfloat162float(h2));
    __nv_bfloat16 l3 = __float2bfloat16_rn(v.w - __bfloat162float(h3));
    lo01 = (uint32_t)__bfloat16_as_ushort(l0) | ((uint32_t)__bfloat16_as_ushort(l1) << 16);
    lo23 = (uint32_t)__bfloat16_as_ushort(l2) | ((uint32_t)__bfloat16_as_ushort(l3) << 16);
}

// ===========================================================================
// fp32 -> bf16 hi/lo split
// ===========================================================================
__global__ void cvt_split(const float4* __restrict__ in, uint2* __restrict__ hi,
                          uint2* __restrict__ lo, int n4)
{
    const int i = blockIdx.x * blockDim.x + threadIdx.x;
    if (i >= n4) return;
    uint32_t h01, h23, l01, l23;
    split4(in[i], h01, h23, l01, l23);
    hi[i] = make_uint2(h01, h23);
    lo[i] = make_uint2(l01, l23);
}

// ===========================================================================
// Fused K/V projection: out_z[M,512] = cond[M,768] @ w_z[512,768]^T, z in {K,V}
// 64x64 tiles, 256 threads (16x16, 4x4 micro), K-chunk 16, M guarded.
// grid (20, 8, 2) = 320 blocks -> full chip.
// ===========================================================================
__global__ __launch_bounds__(256, 4)
void proj_kv(const float* __restrict__ cond, const float* __restrict__ Wk,
             const float* __restrict__ Wv, float* __restrict__ Kout,
             float* __restrict__ Vout)
{
    __shared__ __align__(16) float As[16][64];
    __shared__ __align__(16) float Bs[16][64];

    const float* Bw = blockIdx.z ? Wv : Wk;
    float* C        = blockIdx.z ? Vout : Kout;

    const int tid = threadIdx.x;
    const int tx  = tid & 15;
    const int ty  = tid >> 4;
    const int m0  = blockIdx.x * 64;
    const int n0  = blockIdx.y * 64;
    const int M   = B_ * LK;   // 1232

    const int lr = tid >> 2;          // 0..63 row in tile
    const int lk = (tid & 3) * 4;     // k offset (float4)

    int arow = m0 + lr;
    const bool avalid = (arow < M);
    if (!avalid) arow = M - 1;
    const float* Ap = cond + (size_t)arow * DCOND + lk;
    const float* Bp = Bw + (size_t)(n0 + lr) * DCOND + lk;

    float acc[4][4];
#pragma unroll
    for (int i = 0; i < 4; ++i)
#pragma unroll
        for (int j = 0; j < 4; ++j) acc[i][j] = 0.f;

    for (int kb = 0; kb < DCOND / 16; ++kb) {
        float4 ar = *(const float4*)(Ap + kb * 16);
        if (!avalid) ar = make_float4(0.f, 0.f, 0.f, 0.f);
        const float4 br = *(const float4*)(Bp + kb * 16);
        As[lk + 0][lr] = ar.x; As[lk + 1][lr] = ar.y;
        As[lk + 2][lr] = ar.z; As[lk + 3][lr] = ar.w;
        Bs[lk + 0][lr] = br.x; Bs[lk + 1][lr] = br.y;
        Bs[lk + 2][lr] = br.z; Bs[lk + 3][lr] = br.w;
        __syncthreads();
#pragma unroll
        for (int kk = 0; kk < 16; ++kk) {
            float a[4], b[4];
            *(float4*)a = *(const float4*)&As[kk][ty * 4];
            *(float4*)b = *(const float4*)&Bs[kk][tx * 4];
#pragma unroll
            for (int i = 0; i < 4; ++i)
#pragma unroll
                for (int j = 0; j < 4; ++j) acc[i][j] += a[i] * b[j];
        }
        __syncthreads();
    }

#pragma unroll
    for (int i = 0; i < 4; ++i) {
        const int row = m0 + ty * 4 + i;
        if (row >= M) continue;
        *(float4*)(C + (size_t)row * INNER + n0 + tx * 4) =
            make_float4(acc[i][0], acc[i][1], acc[i][2], acc[i][3]);
    }
}

// ===========================================================================
// HMMA GEMM on pre-split bf16: C = (Ah+Al)(Bh+Bl)^T ≈ AhBh + AhBl + AlBh.
// 128x128 tile, K-chunk 64, 3-stage cp.async pipeline, 256 thr, warp 64x32.
// smem/stage 64KB: {0:Ah,16K:Al,32K:Bh,48K:Bl}, 128x64 bf16 SW128 each.
// ===========================================================================
#define GM_SMEM (3 * 65536)

__global__ void __launch_bounds__(256, 1)
gemm_bf16(const __nv_bfloat16* __restrict__ Ah, const __nv_bfloat16* __restrict__ Al,
          const __nv_bfloat16* __restrict__ Bh, const __nv_bfloat16* __restrict__ Bl,
          float* __restrict__ C)
{
    extern __shared__ char sm[];
    const uint32_t base = smem_u32(sm);
    const int tid  = threadIdx.x;
    const int wid  = tid >> 5;
    const int lane = tid & 31;
    const int wm   = wid & 1;
    const int wn   = wid >> 1;

    const int m0 = blockIdx.x * 128;
    const int n0 = blockIdx.y * 128;
    const __nv_bfloat16* Ah0 = Ah + (size_t)m0 * 512;
    const __nv_bfloat16* Al0 = Al + (size_t)m0 * 512;
    const __nv_bfloat16* Bh0 = Bh + (size_t)n0 * 512;
    const __nv_bfloat16* Bl0 = Bl + (size_t)n0 * 512;

    float acc[4][4][4];
#pragma unroll
    for (int mt = 0; mt < 4; ++mt)
#pragma unroll
        for (int nt = 0; nt < 4; ++nt)
#pragma unroll
            for (int q = 0; q < 4; ++q) acc[mt][nt][q] = 0.f;

    uint32_t aRow0[4], bRow0[4];
#pragma unroll
    for (int mt = 0; mt < 4; ++mt)
        aRow0[mt] = (uint32_t)((wm * 64 + mt * 16 + (lane & 15)) * 128 + (lane >> 4) * 16);
#pragma unroll
    for (int nt = 0; nt < 4; ++nt)
        bRow0[nt] = (uint32_t)((wn * 32 + nt * 8 + (lane & 7)) * 128 + ((lane >> 3) & 1) * 16);

    auto issue_chunk = [&](int c, int buf) {
        const int kc = c * 64;
        const uint32_t tb = base + buf * 65536;
#pragma unroll
        for (int i = 0; i < 4; ++i) {
            const int idx  = i * 256 + tid;
            const int row  = idx >> 3;
            const int c16  = idx & 7;
            const uint32_t so = swz128((uint32_t)(row * 128 + c16 * 16));
            const size_t go = (size_t)row * 512 + kc + c16 * 8;
            cp_async16(tb + so,         Ah0 + go);
            cp_async16(tb + 16384 + so, Al0 + go);
            cp_async16(tb + 32768 + so, Bh0 + go);
            cp_async16(tb + 49152 + so, Bl0 + go);
        }
    };

    issue_chunk(0, 0); CP_COMMIT();
    issue_chunk(1, 1); CP_COMMIT();
    issue_chunk(2, 2); CP_COMMIT();

    for (int c = 0; c < 8; ++c) {
        const int buf = c % 3;
        CP_WAIT2();
        __syncthreads();

        const uint32_t bufA = base + buf * 65536;
        const uint32_t bufB = bufA + 32768;
#pragma unroll
        for (int kb = 0; kb < 4; ++kb) {
            const uint32_t kbyte = kb * 32;
            uint32_t Ahf[4][4], Alf[4][4], Bhf[4][2], Blf[4][2];
#pragma unroll
            for (int mt = 0; mt < 4; ++mt) {
                const uint32_t off = aRow0[mt] + kbyte;
                const uint32_t so  = off ^ ((off >> 3) & 0x70);
                ldmatrix_x4(Ahf[mt], bufA + so);
                ldmatrix_x4(Alf[mt], bufA + 16384 + so);
            }
#pragma unroll
            for (int nt = 0; nt < 4; ++nt) {
                const uint32_t off = bRow0[nt] + kbyte;
                const uint32_t so  = off ^ ((off >> 3) & 0x70);
                ldmatrix_x2(Bhf[nt], bufB + so);
                ldmatrix_x2(Blf[nt], bufB + 16384 + so);
            }
#pragma unroll
            for (int mt = 0; mt < 4; ++mt)
#pragma unroll
                for (int nt = 0; nt < 4; ++nt)
                    mma16816(acc[mt][nt], Ahf[mt], Bhf[nt]);
#pragma unroll
            for (int mt = 0; mt < 4; ++mt)
#pragma unroll
                for (int nt = 0; nt < 4; ++nt)
                    mma16816(acc[mt][nt], Ahf[mt], Blf[nt]);
#pragma unroll
            for (int mt = 0; mt < 4; ++mt)
#pragma unroll
                for (int nt = 0; nt < 4; ++nt)
                    mma16816(acc[mt][nt], Alf[mt], Bhf[nt]);
        }
        __syncthreads();
        if (c + 3 < 8) issue_chunk(c + 3, buf);
        CP_COMMIT();
    }

#pragma unroll
    for (int mt = 0; mt < 4; ++mt) {
        const int r = m0 + wm * 64 + mt * 16 + (lane >> 2);
#pragma unroll
        for (int nt = 0; nt < 4; ++nt) {
            const int cc = n0 + wn * 32 + nt * 8 + (lane & 3) * 2;
            *(float2*)(C + (size_t)r * 512 + cc)       = make_float2(acc[mt][nt][0], acc[mt][nt][1]);
            *(float2*)(C + (size_t)(r + 8) * 512 + cc) = make_float2(acc[mt][nt][2], acc[mt][nt][3]);
        }
    }
}

// ===========================================================================
// Fused attention, query-batched + packed f32x2 FMA. Outputs bf16 hi/lo.
// ===========================================================================
#define KS_PITCH 66
#define VT_PITCH 82
#define ATT_VT_OFF  5084
#define ATT_SCR_OFF (ATT_VT_OFF + 64 * VT_PITCH)
#define ATT_SMEM    ((ATT_SCR_OFF + 8 * 640) * 4)

__global__ __launch_bounds__(256)
void attn_kernel(const float* __restrict__ Q, const float* __restrict__ Kc,
                 const float* __restrict__ Vc,
                 __nv_bfloat16* __restrict__ Ohi, __nv_bfloat16* __restrict__ Olo)
{
    extern __shared__ float smf[];
    float* ks  = smf;                  // [j][d] pitch 66
    float* vt  = smf + ATT_VT_OFF;     // [d][j] pitch 82
    float* scr = smf + ATT_SCR_OFF;

    const int tid = threadIdx.x;
    const int w   = tid >> 5;
    const int l   = tid & 31;
    const int bh  = blockIdx.y;
    const int b   = bh >> 3;
    const int h   = bh & 7;

    const float* kg = Kc + (size_t)b * LK * INNER + h * HD;
    const float* vg = Vc + (size_t)b * LK * INNER + h * HD;
    for (int idx = tid; idx < LK * HD; idx += 256) {
        const int j = idx >> 6, d = idx & 63;
        ks[j * KS_PITCH + d] = kg[(size_t)j * INNER + d];
        vt[d * VT_PITCH + j] = vg[(size_t)j * INNER + d];
    }

    float* pw = scr + w * 640;
    const size_t qbase = ((size_t)b * LQ + blockIdx.x * 64 + w * 8) * INNER + h * HD;
#pragma unroll
    for (int qq = 0; qq < 8; ++qq) {
        const float2 qv = ((const float2*)(Q + qbase + (size_t)qq * INNER))[l];
        pw[qq * 80 + 2 * l]     = qv.x * 0.125f;
        pw[qq * 80 + 2 * l + 1] = qv.y * 0.125f;
    }
    __syncthreads();

    const bool v2 = (l < (LK - 64));
    const int  j2 = v2 ? (64 + l) : 64;
    uint64_t a0[8], a1[8], a2[8];
#pragma unroll
    for (int qq = 0; qq < 8; ++qq) { a0[qq] = 0; a1[qq] = 0; a2[qq] = 0; }

#pragma unroll 4
    for (int d = 0; d < 64; d += 2) {
        const uint64_t k0 = *(const uint64_t*)(ks + l * KS_PITCH + d);
        const uint64_t k1 = *(const uint64_t*)(ks + (l + 32) * KS_PITCH + d);
        const uint64_t k2 = *(const uint64_t*)(ks + j2 * KS_PITCH + d);
#pragma unroll
        for (int qq = 0; qq < 8; ++qq) {
            const uint64_t q2 = *(const uint64_t*)(pw + qq * 80 + d);
            fma2(a0[qq], q2, k0);
            fma2(a1[qq], q2, k1);
            fma2(a2[qq], q2, k2);
        }
    }
    __syncwarp();

    float rs[8];
#pragma unroll
    for (int qq = 0; qq < 8; ++qq) {
        const float s0 = hadd2(a0[qq]);
        const float s1 = hadd2(a1[qq]);
        const float s2v = hadd2(a2[qq]);
        const float s2 = v2 ? s2v : -1e30f;
        float m = fmaxf(s0, fmaxf(s1, s2));
#pragma unroll
        for (int o = 16; o; o >>= 1) m = fmaxf(m, __shfl_xor_sync(0xffffffffu, m, o));
        const float e0 = __expf(s0 - m);
        const float e1 = __expf(s1 - m);
        const float e2 = v2 ? __expf(s2 - m) : 0.f;
        float sum = e0 + e1 + e2;
#pragma unroll
        for (int o = 16; o; o >>= 1) sum += __shfl_xor_sync(0xffffffffu, sum, o);
        rs[qq] = 1.f / sum;
        pw[qq * 80 + l]      = e0;
        pw[qq * 80 + l + 32] = e1;
        if (v2) pw[qq * 80 + 64 + l] = e2;
    }
    __syncwarp();

    uint64_t px[8], py[8];
#pragma unroll
    for (int qq = 0; qq < 8; ++qq) { px[qq] = 0; py[qq] = 0; }

    const float* vr0 = vt + (2 * l) * VT_PITCH;
    const float* vr1 = vt + (2 * l + 1) * VT_PITCH;
#pragma unroll 2
    for (int jp = 0; jp < 76; jp += 2) {
        const uint64_t v0 = *(const uint64_t*)(vr0 + jp);
        const uint64_t v1 = *(const uint64_t*)(vr1 + jp);
#pragma unroll
        for (int qq = 0; qq < 8; ++qq) {
            const uint64_t p2 = *(const uint64_t*)(pw + qq * 80 + jp);
            fma2(px[qq], p2, v0);
            fma2(py[qq], p2, v1);
        }
    }
    const float v0r = vr0[76];
    const float v1r = vr1[76];

#pragma unroll
    for (int qq = 0; qq < 8; ++qq) {
        const float pr = pw[qq * 80 + 76];
        const float ox = (hadd2(px[qq]) + pr * v0r) * rs[qq];
        const float oy = (hadd2(py[qq]) + pr * v1r) * rs[qq];
        const __nv_bfloat16 hx = __float2bfloat16_rn(ox);
        const __nv_bfloat16 hy = __float2bfloat16_rn(oy);
        const __nv_bfloat16 lx = __float2bfloat16_rn(ox - __bfloat162float(hx));
        const __nv_bfloat16 ly = __float2bfloat16_rn(oy - __bfloat162float(hy));
        __nv_bfloat162 hv; hv.x = hx; hv.y = hy;
        __nv_bfloat162 lv; lv.x = lx; lv.y = ly;
        ((__nv_bfloat162*)(Ohi + qbase + (size_t)qq * INNER))[l] = hv;
        ((__nv_bfloat162*)(Olo + qbase + (size_t)qq * INNER))[l] = lv;
    }
}

// ===========================================================================
extern "C" void kernel_launch(void* const* d_in, const int* in_sizes, int n_in,
                              void* d_out, int out_size)
{
    (void)in_sizes; (void)n_in; (void)out_size;
    const float* x    = (const float*)d_in[0];
    const float* cond = (const float*)d_in[1];
    const float* w_q  = (const float*)d_in[2];
    const float* w_k  = (const float*)d_in[3];
    const float* w_v  = (const float*)d_in[4];
    const float* w_o  = (const float*)d_in[5];
    float* out = (float*)d_out;

    float *Qb, *Kb, *Vb;
    __nv_bfloat16 *xhi, *xlo, *ahi, *alo, *wqhi, *wqlo, *wohi, *wolo;
    cudaGetSymbolAddress((void**)&Qb, g_Q);
    cudaGetSymbolAddress((void**)&Kb, g_K);
    cudaGetSymbolAddress((void**)&Vb, g_V);
    cudaGetSymbolAddress((void**)&xhi, g_xhi);
    cudaGetSymbolAddress((void**)&xlo, g_xlo);
    cudaGetSymbolAddress((void**)&ahi, g_ahi);
    cudaGetSymbolAddress((void**)&alo, g_alo);
    cudaGetSymbolAddress((void**)&wqhi, g_wqhi);
    cudaGetSymbolAddress((void**)&wqlo, g_wqlo);
    cudaGetSymbolAddress((void**)&wohi, g_wohi);
    cudaGetSymbolAddress((void**)&wolo, g_wolo);

    cudaFuncSetAttribute(gemm_bf16, cudaFuncAttributeMaxDynamicSharedMemorySize, GM_SMEM);
    cudaFuncSetAttribute(attn_kernel, cudaFuncAttributeMaxDynamicSharedMemorySize, ATT_SMEM);

    // Pre-split to bf16 hi/lo
    const int XN4 = B_ * LQ * DMODEL / 4;
    const int WN4 = DMODEL * INNER / 4;
    cvt_split<<<(XN4 + 255) / 256, 256>>>((const float4*)x, (uint2*)xhi, (uint2*)xlo, XN4);
    cvt_split<<<(WN4 + 255) / 256, 256>>>((const float4*)w_q, (uint2*)wqhi, (uint2*)wqlo, WN4);
    cvt_split<<<(WN4 + 255) / 256, 256>>>((const float4*)w_o, (uint2*)wohi, (uint2*)wolo, WN4);

    // Fused K+V projection: full-chip grid
    proj_kv<<<dim3(20, 8, 2), 256>>>(cond, w_k, w_v, Kb, Vb);

    // Q projection
    gemm_bf16<<<dim3(512, 4), 256, GM_SMEM>>>(xhi, xlo, wqhi, wqlo, Qb);

    // Fused attention -> bf16 hi/lo
    attn_kernel<<<dim3(LQ / 64, B_ * NH), 256, ATT_SMEM>>>(Qb, Kb, Vb, ahi, alo);

    // Output projection
    gemm_bf16<<<dim3(512, 4), 256, GM_SMEM>>>(ahi, alo, wohi, wolo, out);
}

// round 7
// speedup vs baseline: 2.5315x; 1.0356x over previous
#include <cuda_runtime.h>
#include <cuda_bf16.h>
#include <cstdint>
#include <math.h>

#define B_     16
#define LQ     4096
#define LK     77
#define DMODEL 512
#define DCOND  768
#define NH     8
#define HD     64
#define INNER  512   // NH*HD
#define MKV    1232  // B_*LK
#define MKVP   1280  // padded to 128

// Scratch (allocation-free rule: __device__ globals; zero-initialized at load)
__device__ float g_Q[(size_t)B_ * LQ * INNER];
__device__ __nv_bfloat16 g_xhi[(size_t)B_ * LQ * DMODEL];
__device__ __nv_bfloat16 g_xlo[(size_t)B_ * LQ * DMODEL];
__device__ __nv_bfloat16 g_ahi[(size_t)B_ * LQ * INNER];
__device__ __nv_bfloat16 g_alo[(size_t)B_ * LQ * INNER];
__device__ __nv_bfloat16 g_wqhi[DMODEL * INNER];
__device__ __nv_bfloat16 g_wqlo[DMODEL * INNER];
__device__ __nv_bfloat16 g_wohi[DMODEL * INNER];
__device__ __nv_bfloat16 g_wolo[DMODEL * INNER];
__device__ __nv_bfloat16 g_chi[MKVP * DCOND];        // cond split, rows >=1232 stay 0
__device__ __nv_bfloat16 g_clo[MKVP * DCOND];
__device__ __nv_bfloat16 g_wkvhi[2 * INNER * DCOND]; // [w_k ; w_v] rows
__device__ __nv_bfloat16 g_wkvlo[2 * INNER * DCOND];
__device__ float g_KV[(size_t)MKVP * 1024];          // K = cols 0..511, V = 512..1023

// ===========================================================================
// Helpers (base PTX only)
// ===========================================================================
__device__ __forceinline__ uint32_t smem_u32(const void* p) {
    uint32_t a;
    asm("{ .reg .u64 t; cvta.to.shared.u64 t, %1; cvt.u32.u64 %0, t; }" : "=r"(a) : "l"(p));
    return a;
}
__device__ __forceinline__ uint32_t swz128(uint32_t off) { return off ^ ((off >> 3) & 0x70); }

__device__ __forceinline__ void ldmatrix_x4(uint32_t* r, uint32_t addr) {
    asm volatile("ldmatrix.sync.aligned.m8n8.x4.shared.b16 {%0,%1,%2,%3}, [%4];"
        : "=r"(r[0]), "=r"(r[1]), "=r"(r[2]), "=r"(r[3]) : "r"(addr));
}
__device__ __forceinline__ void ldmatrix_x2(uint32_t* r, uint32_t addr) {
    asm volatile("ldmatrix.sync.aligned.m8n8.x2.shared.b16 {%0,%1}, [%2];"
        : "=r"(r[0]), "=r"(r[1]) : "r"(addr));
}
__device__ __forceinline__ void mma16816(float* d, const uint32_t* a, const uint32_t* b) {
    asm volatile("mma.sync.aligned.m16n8k16.row.col.f32.bf16.bf16.f32 "
        "{%0,%1,%2,%3}, {%4,%5,%6,%7}, {%8,%9}, {%0,%1,%2,%3};"
        : "+f"(d[0]), "+f"(d[1]), "+f"(d[2]), "+f"(d[3])
        : "r"(a[0]), "r"(a[1]), "r"(a[2]), "r"(a[3]), "r"(b[0]), "r"(b[1]));
}
__device__ __forceinline__ void cp_async16(uint32_t dst, const void* src) {
    asm volatile("cp.async.cg.shared.global [%0], [%1], 16;" :: "r"(dst), "l"(src));
}
#define CP_COMMIT() asm volatile("cp.async.commit_group;" ::: "memory")
#define CP_WAIT2()  asm volatile("cp.async.wait_group 2;" ::: "memory")

__device__ __forceinline__ void fma2(uint64_t& d, uint64_t a, uint64_t b) {
    asm("fma.rn.f32x2 %0, %1, %2, %0;" : "+l"(d) : "l"(a), "l"(b));
}
__device__ __forceinline__ float hadd2(uint64_t v) {
    float lo, hi;
    asm("mov.b64 {%0,%1}, %2;" : "=f"(lo), "=f"(hi) : "l"(v));
    return lo + hi;
}

__device__ __forceinline__ void split4(float4 v, uint32_t& hi01, uint32_t& hi23,
                                       uint32_t& lo01, uint32_t& lo23) {
    __nv_bfloat16 h0 = __float2bfloat16_rn(v.x), h1 = __float2bfloat16_rn(v.y);
    __nv_bfloat16 h2 = __float2bfloat16_rn(v.z), h3 = __float2bfloat16_rn(v.w);
    hi01 = (uint32_t)__bfloat16_as_ushort(h0) | ((uint32_t)__bfloat16_as_ushort(h1) << 16);
    hi23 = (uint32_t)__bfloat16_as_ushort(h2) | ((uint32_t)__bfloat16_as_ushort(h3) << 16);
    __nv_bfloat16 l0 = __float2bfloat16_rn(v.x - __bfloat162float(h0));
    __nv_bfloat16 l1 = __float2bfloat16_rn(v.y - __bfloat162float(h1));
    __nv_bfloat16 l2 = __float2bfloat16_rn(v.z - __bfloat162float(h2));
    __nv_bfloat16 l3 = __float2bfloat16_rn(v.w - __bfloat162float(h3));
    lo01 = (uint32_t)__bfloat16_as_ushort(l0) | ((uint32_t)__bfloat16_as_ushort(l1) << 16);
    lo23 = (uint32_t)__bfloat16_as_ushort(l2) | ((uint32_t)__bfloat16_as_ushort(l3) << 16);
}

__global__ void cvt_split(const float4* __restrict__ in, uint2* __restrict__ hi,
                          uint2* __restrict__ lo, int n4)
{
    const int i = blockIdx.x * blockDim.x + threadIdx.x;
    if (i >= n4) return;
    uint32_t h01, h23, l01, l23;
    split4(in[i], h01, h23, l01, l23);
    hi[i] = make_uint2(h01, h23);
    lo[i] = make_uint2(l01, l23);
}

// ===========================================================================
// HMMA GEMM on pre-split bf16: C[M,*] = (Ah+Al)[M,KDIM] @ (Bh+Bl)[N,KDIM]^T
//   ≈ AhBh + AhBl + AlBh.  fp32 C, row stride LDC.
// 128x128 tile, K-chunk 64, 3-stage cp.async pipeline.
// 512 threads (16 warps, 4x4), warp tile 32x32 -> low regs, 16 warps/SM.
// smem/stage 64KB: {0:Ah,16K:Al,32K:Bh,48K:Bl}, 128x64 bf16 SW128 each.
// ===========================================================================
#define GM_SMEM (3 * 65536)

template <int KDIM, int LDC>
__global__ void __launch_bounds__(512, 1)
gemm_bf16(const __nv_bfloat16* __restrict__ Ah, const __nv_bfloat16* __restrict__ Al,
          const __nv_bfloat16* __restrict__ Bh, const __nv_bfloat16* __restrict__ Bl,
          float* __restrict__ C)
{
    constexpr int NCHUNK = KDIM / 64;
    extern __shared__ char sm[];
    const uint32_t base = smem_u32(sm);
    const int tid  = threadIdx.x;
    const int wid  = tid >> 5;
    const int lane = tid & 31;
    const int wm   = wid & 3;    // 4 m-blocks of 32
    const int wn   = wid >> 2;   // 4 n-blocks of 32

    const int m0 = blockIdx.x * 128;
    const int n0 = blockIdx.y * 128;
    const __nv_bfloat16* Ah0 = Ah + (size_t)m0 * KDIM;
    const __nv_bfloat16* Al0 = Al + (size_t)m0 * KDIM;
    const __nv_bfloat16* Bh0 = Bh + (size_t)n0 * KDIM;
    const __nv_bfloat16* Bl0 = Bl + (size_t)n0 * KDIM;

    float acc[2][4][4];
#pragma unroll
    for (int mt = 0; mt < 2; ++mt)
#pragma unroll
        for (int nt = 0; nt < 4; ++nt)
#pragma unroll
            for (int q = 0; q < 4; ++q) acc[mt][nt][q] = 0.f;

    uint32_t aRow0[2], bRow0[4];
#pragma unroll
    for (int mt = 0; mt < 2; ++mt)
        aRow0[mt] = (uint32_t)((wm * 32 + mt * 16 + (lane & 15)) * 128 + (lane >> 4) * 16);
#pragma unroll
    for (int nt = 0; nt < 4; ++nt)
        bRow0[nt] = (uint32_t)((wn * 32 + nt * 8 + (lane & 7)) * 128 + ((lane >> 3) & 1) * 16);

    // stage one chunk: 4 tiles x 1024 x 16B = 4096 cp.async; 8 per thread
    auto issue_chunk = [&](int c, int buf) {
        const int kc = c * 64;
        const uint32_t tb = base + buf * 65536;
#pragma unroll
        for (int i = 0; i < 2; ++i) {
            const int idx  = i * 512 + tid;      // 0..1023
            const int row  = idx >> 3;
            const int c16  = idx & 7;
            const uint32_t so = swz128((uint32_t)(row * 128 + c16 * 16));
            const size_t go = (size_t)row * KDIM + kc + c16 * 8;
            cp_async16(tb + so,         Ah0 + go);
            cp_async16(tb + 16384 + so, Al0 + go);
            cp_async16(tb + 32768 + so, Bh0 + go);
            cp_async16(tb + 49152 + so, Bl0 + go);
        }
    };

    issue_chunk(0, 0); CP_COMMIT();
    issue_chunk(1, 1); CP_COMMIT();
    issue_chunk(2, 2); CP_COMMIT();

    for (int c = 0; c < NCHUNK; ++c) {
        const int buf = c % 3;
        CP_WAIT2();
        __syncthreads();

        const uint32_t bufA = base + buf * 65536;
        const uint32_t bufB = bufA + 32768;
#pragma unroll
        for (int kb = 0; kb < 4; ++kb) {
            const uint32_t kbyte = kb * 32;
            uint32_t Ahf[2][4], Alf[2][4], Bhf[4][2], Blf[4][2];
#pragma unroll
            for (int mt = 0; mt < 2; ++mt) {
                const uint32_t off = aRow0[mt] + kbyte;
                const uint32_t so  = off ^ ((off >> 3) & 0x70);
                ldmatrix_x4(Ahf[mt], bufA + so);
                ldmatrix_x4(Alf[mt], bufA + 16384 + so);
            }
#pragma unroll
            for (int nt = 0; nt < 4; ++nt) {
                const uint32_t off = bRow0[nt] + kbyte;
                const uint32_t so  = off ^ ((off >> 3) & 0x70);
                ldmatrix_x2(Bhf[nt], bufB + so);
                ldmatrix_x2(Blf[nt], bufB + 16384 + so);
            }
#pragma unroll
            for (int mt = 0; mt < 2; ++mt)
#pragma unroll
                for (int nt = 0; nt < 4; ++nt)
                    mma16816(acc[mt][nt], Ahf[mt], Bhf[nt]);
#pragma unroll
            for (int mt = 0; mt < 2; ++mt)
#pragma unroll
                for (int nt = 0; nt < 4; ++nt)
                    mma16816(acc[mt][nt], Ahf[mt], Blf[nt]);
#pragma unroll
            for (int mt = 0; mt < 2; ++mt)
#pragma unroll
                for (int nt = 0; nt < 4; ++nt)
                    mma16816(acc[mt][nt], Alf[mt], Bhf[nt]);
        }
        __syncthreads();
        if (c + 3 < NCHUNK) issue_chunk(c + 3, buf);
        CP_COMMIT();
    }

#pragma unroll
    for (int mt = 0; mt < 2; ++mt) {
        const int r = m0 + wm * 32 + mt * 16 + (lane >> 2);
#pragma unroll
        for (int nt = 0; nt < 4; ++nt) {
            const int cc = n0 + wn * 32 + nt * 8 + (lane & 3) * 2;
            *(float2*)(C + (size_t)r * LDC + cc)       = make_float2(acc[mt][nt][0], acc[mt][nt][1]);
            *(float2*)(C + (size_t)(r + 8) * LDC + cc) = make_float2(acc[mt][nt][2], acc[mt][nt][3]);
        }
    }
}

// ===========================================================================
// Fused attention (reads K/V from fused g_KV, row stride 1024).
// ===========================================================================
#define KS_PITCH 66
#define VT_PITCH 82
#define ATT_VT_OFF  5084
#define ATT_SCR_OFF (ATT_VT_OFF + 64 * VT_PITCH)
#define ATT_SMEM    ((ATT_SCR_OFF + 8 * 640) * 4)

__global__ __launch_bounds__(256)
void attn_kernel(const float* __restrict__ Q, const float* __restrict__ KV,
                 __nv_bfloat16* __restrict__ Ohi, __nv_bfloat16* __restrict__ Olo)
{
    extern __shared__ float smf[];
    float* ks  = smf;                  // [j][d] pitch 66
    float* vt  = smf + ATT_VT_OFF;     // [d][j] pitch 82
    float* scr = smf + ATT_SCR_OFF;

    const int tid = threadIdx.x;
    const int w   = tid >> 5;
    const int l   = tid & 31;
    const int bh  = blockIdx.y;
    const int b   = bh >> 3;
    const int h   = bh & 7;

    const float* kg = KV + (size_t)b * LK * 1024 + h * HD;
    const float* vg = kg + 512;
    for (int idx = tid; idx < LK * HD; idx += 256) {
        const int j = idx >> 6, d = idx & 63;
        ks[j * KS_PITCH + d] = kg[(size_t)j * 1024 + d];
        vt[d * VT_PITCH + j] = vg[(size_t)j * 1024 + d];
    }

    float* pw = scr + w * 640;
    const size_t qbase = ((size_t)b * LQ + blockIdx.x * 64 + w * 8) * INNER + h * HD;
#pragma unroll
    for (int qq = 0; qq < 8; ++qq) {
        const float2 qv = ((const float2*)(Q + qbase + (size_t)qq * INNER))[l];
        pw[qq * 80 + 2 * l]     = qv.x * 0.125f;
        pw[qq * 80 + 2 * l + 1] = qv.y * 0.125f;
    }
    __syncthreads();

    const bool v2 = (l < (LK - 64));
    const int  j2 = v2 ? (64 + l) : 64;
    uint64_t a0[8], a1[8], a2[8];
#pragma unroll
    for (int qq = 0; qq < 8; ++qq) { a0[qq] = 0; a1[qq] = 0; a2[qq] = 0; }

#pragma unroll 4
    for (int d = 0; d < 64; d += 2) {
        const uint64_t k0 = *(const uint64_t*)(ks + l * KS_PITCH + d);
        const uint64_t k1 = *(const uint64_t*)(ks + (l + 32) * KS_PITCH + d);
        const uint64_t k2 = *(const uint64_t*)(ks + j2 * KS_PITCH + d);
#pragma unroll
        for (int qq = 0; qq < 8; ++qq) {
            const uint64_t q2 = *(const uint64_t*)(pw + qq * 80 + d);
            fma2(a0[qq], q2, k0);
            fma2(a1[qq], q2, k1);
            fma2(a2[qq], q2, k2);
        }
    }
    __syncwarp();

    float rs[8];
#pragma unroll
    for (int qq = 0; qq < 8; ++qq) {
        const float s0 = hadd2(a0[qq]);
        const float s1 = hadd2(a1[qq]);
        const float s2v = hadd2(a2[qq]);
        const float s2 = v2 ? s2v : -1e30f;
        float m = fmaxf(s0, fmaxf(s1, s2));
#pragma unroll
        for (int o = 16; o; o >>= 1) m = fmaxf(m, __shfl_xor_sync(0xffffffffu, m, o));
        const float e0 = __expf(s0 - m);
        const float e1 = __expf(s1 - m);
        const float e2 = v2 ? __expf(s2 - m) : 0.f;
        float sum = e0 + e1 + e2;
#pragma unroll
        for (int o = 16; o; o >>= 1) sum += __shfl_xor_sync(0xffffffffu, sum, o);
        rs[qq] = 1.f / sum;
        pw[qq * 80 + l]      = e0;
        pw[qq * 80 + l + 32] = e1;
        if (v2) pw[qq * 80 + 64 + l] = e2;
    }
    __syncwarp();

    uint64_t px[8], py[8];
#pragma unroll
    for (int qq = 0; qq < 8; ++qq) { px[qq] = 0; py[qq] = 0; }

    const float* vr0 = vt + (2 * l) * VT_PITCH;
    const float* vr1 = vt + (2 * l + 1) * VT_PITCH;
#pragma unroll 2
    for (int jp = 0; jp < 76; jp += 2) {
        const uint64_t v0 = *(const uint64_t*)(vr0 + jp);
        const uint64_t v1 = *(const uint64_t*)(vr1 + jp);
#pragma unroll
        for (int qq = 0; qq < 8; ++qq) {
            const uint64_t p2 = *(const uint64_t*)(pw + qq * 80 + jp);
            fma2(px[qq], p2, v0);
            fma2(py[qq], p2, v1);
        }
    }
    const float v0r = vr0[76];
    const float v1r = vr1[76];

#pragma unroll
    for (int qq = 0; qq < 8; ++qq) {
        const float pr = pw[qq * 80 + 76];
        const float ox = (hadd2(px[qq]) + pr * v0r) * rs[qq];
        const float oy = (hadd2(py[qq]) + pr * v1r) * rs[qq];
        const __nv_bfloat16 hx = __float2bfloat16_rn(ox);
        const __nv_bfloat16 hy = __float2bfloat16_rn(oy);
        const __nv_bfloat16 lx = __float2bfloat16_rn(ox - __bfloat162float(hx));
        const __nv_bfloat16 ly = __float2bfloat16_rn(oy - __bfloat162float(hy));
        __nv_bfloat162 hv; hv.x = hx; hv.y = hy;
        __nv_bfloat162 lv; lv.x = lx; lv.y = ly;
        ((__nv_bfloat162*)(Ohi + qbase + (size_t)qq * INNER))[l] = hv;
        ((__nv_bfloat162*)(Olo + qbase + (size_t)qq * INNER))[l] = lv;
    }
}

// ===========================================================================
extern "C" void kernel_launch(void* const* d_in, const int* in_sizes, int n_in,
                              void* d_out, int out_size)
{
    (void)in_sizes; (void)n_in; (void)out_size;
    const float* x    = (const float*)d_in[0];
    const float* cond = (const float*)d_in[1];
    const float* w_q  = (const float*)d_in[2];
    const float* w_k  = (const float*)d_in[3];
    const float* w_v  = (const float*)d_in[4];
    const float* w_o  = (const float*)d_in[5];
    float* out = (float*)d_out;

    float *Qb, *KVb;
    __nv_bfloat16 *xhi, *xlo, *ahi, *alo, *wqhi, *wqlo, *wohi, *wolo;
    __nv_bfloat16 *chi, *clo, *wkvhi, *wkvlo;
    cudaGetSymbolAddress((void**)&Qb, g_Q);
    cudaGetSymbolAddress((void**)&KVb, g_KV);
    cudaGetSymbolAddress((void**)&xhi, g_xhi);
    cudaGetSymbolAddress((void**)&xlo, g_xlo);
    cudaGetSymbolAddress((void**)&ahi, g_ahi);
    cudaGetSymbolAddress((void**)&alo, g_alo);
    cudaGetSymbolAddress((void**)&wqhi, g_wqhi);
    cudaGetSymbolAddress((void**)&wqlo, g_wqlo);
    cudaGetSymbolAddress((void**)&wohi, g_wohi);
    cudaGetSymbolAddress((void**)&wolo, g_wolo);
    cudaGetSymbolAddress((void**)&chi, g_chi);
    cudaGetSymbolAddress((void**)&clo, g_clo);
    cudaGetSymbolAddress((void**)&wkvhi, g_wkvhi);
    cudaGetSymbolAddress((void**)&wkvlo, g_wkvlo);

    cudaFuncSetAttribute(gemm_bf16<512, 512>,  cudaFuncAttributeMaxDynamicSharedMemorySize, GM_SMEM);
    cudaFuncSetAttribute(gemm_bf16<768, 1024>, cudaFuncAttributeMaxDynamicSharedMemorySize, GM_SMEM);
    cudaFuncSetAttribute(attn_kernel, cudaFuncAttributeMaxDynamicSharedMemorySize, ATT_SMEM);

    // Pre-split to bf16 hi/lo
    const int XN4 = B_ * LQ * DMODEL / 4;
    const int WN4 = DMODEL * INNER / 4;
    const int CN4 = MKV * DCOND / 4;
    const int WKN4 = INNER * DCOND / 4;
    cvt_split<<<(XN4 + 255) / 256, 256>>>((const float4*)x, (uint2*)xhi, (uint2*)xlo, XN4);
    cvt_split<<<(WN4 + 255) / 256, 256>>>((const float4*)w_q, (uint2*)wqhi, (uint2*)wqlo, WN4);
    cvt_split<<<(WN4 + 255) / 256, 256>>>((const float4*)w_o, (uint2*)wohi, (uint2*)wolo, WN4);
    cvt_split<<<(CN4 + 255) / 256, 256>>>((const float4*)cond, (uint2*)chi, (uint2*)clo, CN4);
    cvt_split<<<(WKN4 + 255) / 256, 256>>>((const float4*)w_k, (uint2*)wkvhi, (uint2*)wkvlo, WKN4);
    cvt_split<<<(WKN4 + 255) / 256, 256>>>((const float4*)w_v,
        (uint2*)(wkvhi + (size_t)INNER * DCOND), (uint2*)(wkvlo + (size_t)INNER * DCOND), WKN4);

    // K+V projection in ONE tensor-core GEMM: [1280,768] @ [1024,768]^T -> g_KV
    gemm_bf16<768, 1024><<<dim3(MKVP / 128, 8), 512, GM_SMEM>>>(chi, clo, wkvhi, wkvlo, KVb);

    // Q projection
    gemm_bf16<512, 512><<<dim3(512, 4), 512, GM_SMEM>>>(xhi, xlo, wqhi, wqlo, Qb);

    // Fused attention -> bf16 hi/lo
    attn_kernel<<<dim3(LQ / 64, B_ * NH), 256, ATT_SMEM>>>(Qb, KVb, ahi, alo);

    // Output projection
    gemm_bf16<512, 512><<<dim3(512, 4), 512, GM_SMEM>>>(ahi, alo, wohi, wolo, out);
}